// round 10
// baseline (speedup 1.0000x reference)
#include <cuda_runtime.h>
#include <cuda_bf16.h>
#include <math.h>
#include <stdint.h>

#define B_ 2
#define N_ 1280
#define C_ 1024
#define H_ 16
#define DH 64
#define I_ 4096
#define T_ 256
#define L1_ 4
#define BH_ (B_*H_)

// ---- fp32 scratch ----
__device__ float g_q[(size_t)BH_ * N_ * DH];
__device__ float g_k[(size_t)BH_ * N_ * DH];
__device__ float g_s[(size_t)BH_ * N_ * N_];
__device__ float g_h[(size_t)B_ * N_ * C_];
__device__ float g_g[(size_t)B_ * N_ * I_];
__device__ float g_u[(size_t)B_ * N_ * I_];
__device__ float g_ps[2][(size_t)B_ * N_ * C_];   // split-K partials for down
// ---- bf16 hi/lo scratch ----
__device__ __align__(16) __nv_bfloat16 xn_h[(size_t)B_*N_*C_], xn_l[(size_t)B_*N_*C_];
__device__ __align__(16) __nv_bfloat16 q_h[(size_t)BH_*N_*DH], q_l[(size_t)BH_*N_*DH];
__device__ __align__(16) __nv_bfloat16 k_h[(size_t)BH_*N_*DH], k_l[(size_t)BH_*N_*DH];
__device__ __align__(16) __nv_bfloat16 vt_h[(size_t)BH_*DH*N_], vt_l[(size_t)BH_*DH*N_];
__device__ __align__(16) __nv_bfloat16 p_h[(size_t)BH_*N_*N_], p_l[(size_t)BH_*N_*N_];
__device__ __align__(16) __nv_bfloat16 ao_h[(size_t)B_*N_*C_], ao_l[(size_t)B_*N_*C_];
__device__ __align__(16) __nv_bfloat16 gg_h[(size_t)B_*N_*I_], gg_l[(size_t)B_*N_*I_];
__device__ __align__(16) __nv_bfloat16 wqkv_h[(size_t)3*3072*1024], wqkv_l[(size_t)3*3072*1024];
__device__ __align__(16) __nv_bfloat16 wprj_h[(size_t)3*1024*1024], wprj_l[(size_t)3*1024*1024];
__device__ __align__(16) __nv_bfloat16 wgat_h[(size_t)3*4096*1024], wgat_l[(size_t)3*4096*1024];
__device__ __align__(16) __nv_bfloat16 wup_h [(size_t)3*4096*1024], wup_l [(size_t)3*4096*1024];
__device__ __align__(16) __nv_bfloat16 wdn_h [(size_t)3*1024*4096], wdn_l [(size_t)3*1024*4096];

// ---- block-sparse tables (128x128) ----
__constant__ int c_PAIRQ[39] = {0, 1,1, 2,2,2, 3,3,3,3, 4,4,4,4,4, 5,5,5,5,5,5,
                                6,6,6, 7,7,7,7, 8,8,8,8,8, 9,9,9,9,9,9};
__constant__ int c_PAIRK[39] = {0, 0,1, 0,1,2, 0,1,2,3, 0,1,2,3,4, 0,1,2,3,4,5,
                                0,1,6, 0,1,2,7, 0,1,2,3,8, 0,1,2,3,4,9};
__constant__ int c_KCNT[10] = {1,2,3,4,5,6,3,4,5,6};
__constant__ int c_KLIST[10][6] = {
    {0,0,0,0,0,0},{0,1,0,0,0,0},{0,1,2,0,0,0},{0,1,2,3,0,0},{0,1,2,3,4,0},
    {0,1,2,3,4,5},{0,1,6,0,0,0},{0,1,2,7,0,0},{0,1,2,3,8,0},{0,1,2,3,4,9}};
// attnV qrow order: descending work so long CTAs start in wave 1
__constant__ int c_QORD[10] = {5,9,4,8,3,7,2,6,1,0};

// ---- helpers ----
__device__ __forceinline__ uint32_t s2u(const void* p) {
    uint32_t a;
    asm("{ .reg .u64 t; cvta.to.shared.u64 t, %1; cvt.u32.u64 %0, t; }" : "=r"(a) : "l"(p));
    return a;
}
__device__ __forceinline__ void split2(float v, __nv_bfloat16* h, __nv_bfloat16* l) {
    __nv_bfloat16 hh = __float2bfloat16(v);
    *h = hh; *l = __float2bfloat16(v - __bfloat162float(hh));
}
__device__ __forceinline__ float warpSum(float v){
    #pragma unroll
    for (int o=16;o;o>>=1) v += __shfl_xor_sync(0xffffffffu,v,o);
    return v;
}
__device__ __forceinline__ float warpMax(float v){
    #pragma unroll
    for (int o=16;o;o>>=1) v = fmaxf(v,__shfl_xor_sync(0xffffffffu,v,o));
    return v;
}
#define LDM4(r, a) asm volatile("ldmatrix.sync.aligned.m8n8.x4.shared.b16 {%0,%1,%2,%3}, [%4];" \
    : "=r"((r)[0]),"=r"((r)[1]),"=r"((r)[2]),"=r"((r)[3]) : "r"(a))
#define LDM2(r, a) asm volatile("ldmatrix.sync.aligned.m8n8.x2.shared.b16 {%0,%1}, [%2];" \
    : "=r"((r)[0]),"=r"((r)[1]) : "r"(a))
#define MMA(d, a, b) asm volatile( \
    "mma.sync.aligned.m16n8k16.row.col.f32.bf16.bf16.f32 {%0,%1,%2,%3}, {%4,%5,%6,%7}, {%8,%9}, {%0,%1,%2,%3};" \
    : "+f"((d)[0]),"+f"((d)[1]),"+f"((d)[2]),"+f"((d)[3]) \
    : "r"((a)[0]),"r"((a)[1]),"r"((a)[2]),"r"((a)[3]),"r"((b)[0]),"r"((b)[1]))
#define CPCG() asm volatile("cp.async.commit_group;" ::: "memory")

// BK=32 tile: row stride 80B; 8 consecutive rows hit distinct 16B bank groups.
__device__ __forceinline__ void ldt32(uint32_t dstB, const __nv_bfloat16* g, int ld, int rows, int tid) {
    for (int i = tid; i < rows * 4; i += 256) {
        int r = i >> 2, q = i & 3;
        uint32_t d = dstB + (uint32_t)(r * 80 + q * 16);
        const void* s = g + (size_t)r * ld + q * 8;
        asm volatile("cp.async.cg.shared.global [%0], [%1], 16;" :: "r"(d), "l"(s));
    }
}

// ---- split-bf16 HMMA GEMM: 128 x BN block, 8 warps (2x4), BK=32, 3-stage, 1 sync/iter ----
// EPI: 0 qkv  1 scores(sparse)  2 attnV(sparse K, reordered)  3 proj  7 down split-K  8 gate+up fused
template <int BN, int EPI>
__global__ void __launch_bounds__(256) mmagemm_k(
    const __nv_bfloat16* __restrict__ Ah, const __nv_bfloat16* __restrict__ Al,
    const __nv_bfloat16* __restrict__ Bh, const __nv_bfloat16* __restrict__ Bl,
    const float* __restrict__ bias, const float* __restrict__ aux,
    float* __restrict__ Cout, int K, int ldab, long sA, long sB, int segw)
{
    constexpr int ATB = 128 * 80;
    constexpr int BTB = BN * 80;
    constexpr int SSB = 2 * ATB + 2 * BTB;
    constexpr int NW = BN / 4;
    constexpr int NT = NW / 8;
    extern __shared__ __align__(16) char smc[];
    const uint32_t sb = s2u(smc);
    const int tid = threadIdx.x, wid = tid >> 5, lane = tid & 31;
    const int wm = wid & 1, wn = wid >> 1;
    const int z = blockIdx.z;

    int brow, bcol;
    if constexpr (EPI == 1) { brow = c_PAIRQ[blockIdx.x] * 128; bcol = c_PAIRK[blockIdx.x] * 128; }
    else if constexpr (EPI == 2) { brow = c_QORD[blockIdx.y] * 128; bcol = blockIdx.x * BN; }
    else { brow = blockIdx.y * 128; bcol = blockIdx.x * BN; }

    const int* kl = nullptr;
    int nc;
    if constexpr (EPI == 2) { int qr = brow >> 7; kl = c_KLIST[qr]; nc = c_KCNT[qr] * 4; }
    else nc = K >> 5;

    int seg = 0;
    if (segw) { int n0 = brow % N_; seg = n0 < T_ ? 0 : (n0 < 768 ? 1 : 2); }
    int koff = 0;
    if constexpr (EPI == 7) koff = z * 2048;
    long zA = (EPI == 7) ? 0 : (long)z;
    const __nv_bfloat16* pAh = Ah + (size_t)zA * sA + (size_t)brow * ldab + koff;
    const __nv_bfloat16* pAl = Al + (size_t)zA * sA + (size_t)brow * ldab + koff;
    size_t boff = segw ? (size_t)seg * sB : (size_t)zA * sB;
    const __nv_bfloat16 *pBh, *pBl;
    if constexpr (EPI == 8) {
        if (bcol < I_) { pBh = Bh + boff + (size_t)bcol * ldab; pBl = Bl + boff + (size_t)bcol * ldab; }
        else {
            pBh = (const __nv_bfloat16*)bias + boff + (size_t)(bcol - I_) * ldab;
            pBl = (const __nv_bfloat16*)aux  + boff + (size_t)(bcol - I_) * ldab;
        }
    } else {
        pBh = Bh + boff + (size_t)bcol * ldab + koff;
        pBl = Bl + boff + (size_t)bcol * ldab + koff;
    }

    auto kcof = [&](int c) -> int {
        if constexpr (EPI == 2) return (kl[c >> 2] << 7) + (c & 3) * 32;
        else return c << 5;
    };
    auto load_stage = [&](int s, int kc) {
        uint32_t st = sb + (uint32_t)s * SSB;
        ldt32(st,               pAh + kc, ldab, 128, tid);
        ldt32(st + ATB,         pAl + kc, ldab, 128, tid);
        ldt32(st + 2*ATB,       pBh + kc, ldab, BN, tid);
        ldt32(st + 2*ATB + BTB, pBl + kc, ldab, BN, tid);
    };

    float acc[4][NT][4];
    #pragma unroll
    for (int i = 0; i < 4; i++)
        #pragma unroll
        for (int j = 0; j < NT; j++)
            #pragma unroll
            for (int p = 0; p < 4; p++) acc[i][j][p] = 0.f;

    load_stage(0, kcof(0));
    CPCG();
    if (nc > 1) load_stage(1, kcof(1));
    CPCG();

    const int lt = lane & 15;
    const uint32_t aoffH = (uint32_t)((wm * 64 + lt) * 80 + (lane >> 4) * 16);
    const uint32_t boff0 = (uint32_t)((wn * NW + (lt & 7)) * 80 + (lt >> 3) * 16);

    for (int c = 0; c < nc; c++) {
        // stage c ready for all threads; compute(c-1) done by all before its
        // buffer ((c+2)%3 == (c-1)%3) is overwritten below.
        asm volatile("cp.async.wait_group 1;" ::: "memory");
        __syncthreads();
        if (c + 2 < nc) load_stage((c + 2) % 3, kcof(c + 2));
        CPCG();
        uint32_t st = sb + (uint32_t)(c % 3) * SSB;
        #pragma unroll
        for (int kk = 0; kk < 2; kk++) {
            uint32_t ah[4][4], al[4][4];
            #pragma unroll
            for (int mt = 0; mt < 4; mt++) {
                uint32_t a = st + aoffH + (uint32_t)(mt * 16 * 80) + (uint32_t)(kk * 32);
                LDM4(ah[mt], a);
                LDM4(al[mt], a + ATB);
            }
            #pragma unroll
            for (int nt = 0; nt < NT; nt++) {
                uint32_t bh[2], bl[2];
                uint32_t b = st + 2*ATB + boff0 + (uint32_t)(nt * 8 * 80) + (uint32_t)(kk * 32);
                LDM2(bh, b);
                LDM2(bl, b + BTB);
                #pragma unroll
                for (int mt = 0; mt < 4; mt++) {
                    MMA(acc[mt][nt], ah[mt], bh);
                    MMA(acc[mt][nt], ah[mt], bl);
                    MMA(acc[mt][nt], al[mt], bh);
                }
            }
        }
    }

    // ---- epilogue ----
    #pragma unroll
    for (int mt = 0; mt < 4; mt++) {
        #pragma unroll
        for (int nt = 0; nt < NT; nt++) {
            #pragma unroll
            for (int p = 0; p < 2; p++) {
                int m = brow + wm * 64 + mt * 16 + (lane >> 2) + p * 8;
                #pragma unroll
                for (int j = 0; j < 2; j++) {
                    int cg = bcol + wn * NW + nt * 8 + (lane & 3) * 2 + j;
                    float v = acc[mt][nt][p * 2 + j];
                    if constexpr (EPI == 0) {
                        v += bias[seg * 3 * C_ + cg];
                        int b = m >= N_; int n = m - b * N_;
                        int which = cg >> 10, h = (cg >> 6) & 15, dd = cg & 63;
                        if (which == 0) g_q[(((size_t)(b*H_+h))*N_ + n)*DH + dd] = v;
                        else if (which == 1) g_k[(((size_t)(b*H_+h))*N_ + n)*DH + dd] = v;
                        else { size_t vi = (((size_t)(b*H_+h))*DH + dd)*N_ + n; split2(v, &vt_h[vi], &vt_l[vi]); }
                    } else if constexpr (EPI == 1) {
                        g_s[((size_t)z*N_ + m)*N_ + cg] = v;   // q pre-scaled by 1/8
                    } else if constexpr (EPI == 2) {
                        int b = z >> 4, h = z & 15;
                        size_t ai = ((size_t)(b*N_ + m))*C_ + h*DH + cg;
                        split2(v, &ao_h[ai], &ao_l[ai]);
                    } else if constexpr (EPI == 3) {
                        size_t idx = (size_t)m * C_ + cg;
                        g_h[idx] = aux[idx] + v + bias[seg * C_ + cg];
                    } else if constexpr (EPI == 7) {
                        g_ps[z][(size_t)m * C_ + cg] = v;
                    } else {   // EPI 8: gate | up
                        if (cg < I_) g_g[(size_t)m * I_ + cg] = v;
                        else         g_u[(size_t)m * I_ + cg - I_] = v;
                    }
                }
            }
        }
    }
    (void)Cout;
}

// ---- down reduce: out = g_h + ps0 + ps1 ----
__global__ void __launch_bounds__(256) reduce_k(float* __restrict__ out) {
    size_t i = ((size_t)blockIdx.x * 256 + threadIdx.x) * 4;
    float4 h = *(float4*)(g_h + i);
    float4 a = *(float4*)(&g_ps[0][i]);
    float4 b = *(float4*)(&g_ps[1][i]);
    float4 o;
    o.x = h.x + a.x + b.x; o.y = h.y + a.y + b.y;
    o.z = h.z + a.z + b.z; o.w = h.w + a.w + b.w;
    *(float4*)(out + i) = o;
}

// ---- weight transpose + hi/lo convert (vectorized): W[K,N] -> T[N,K], 32x128 tiles ----
__global__ void __launch_bounds__(256) transconv_k(const float* __restrict__ W,
    __nv_bfloat16* __restrict__ Th, __nv_bfloat16* __restrict__ Tl, int K, int N) {
    __shared__ float t[32][129];
    int sg = blockIdx.z;
    W += (size_t)sg * K * N; Th += (size_t)sg * K * N; Tl += (size_t)sg * K * N;
    int n0 = blockIdx.x * 128, k0 = blockIdx.y * 32;
    int tid = threadIdx.x;
    #pragma unroll
    for (int i = 0; i < 4; i++) {
        int id = tid + i * 256;
        int r = id >> 5, c4 = (id & 31) * 4;
        float4 v = *(const float4*)(W + (size_t)(k0 + r) * N + n0 + c4);
        t[r][c4] = v.x; t[r][c4+1] = v.y; t[r][c4+2] = v.z; t[r][c4+3] = v.w;
    }
    __syncthreads();
    int n = tid >> 1, hf = (tid & 1) * 16;
    uint32_t hb[8], lb[8];
    #pragma unroll
    for (int kk = 0; kk < 16; kk += 2) {
        float a = t[hf + kk][n], b = t[hf + kk + 1][n];
        __nv_bfloat16 ah = __float2bfloat16(a), bh = __float2bfloat16(b);
        __nv_bfloat16 alo = __float2bfloat16(a - __bfloat162float(ah));
        __nv_bfloat16 blo = __float2bfloat16(b - __bfloat162float(bh));
        hb[kk >> 1] = (uint32_t)__bfloat16_as_ushort(bh) << 16 | __bfloat16_as_ushort(ah);
        lb[kk >> 1] = (uint32_t)__bfloat16_as_ushort(blo) << 16 | __bfloat16_as_ushort(alo);
    }
    size_t o = (size_t)(n0 + n) * K + k0 + hf;
    *(uint4*)(Th + o)     = make_uint4(hb[0], hb[1], hb[2], hb[3]);
    *(uint4*)(Th + o + 8) = make_uint4(hb[4], hb[5], hb[6], hb[7]);
    *(uint4*)(Tl + o)     = make_uint4(lb[0], lb[1], lb[2], lb[3]);
    *(uint4*)(Tl + o + 8) = make_uint4(lb[4], lb[5], lb[6], lb[7]);
}

// ---- RMS norm -> hi/lo ----
__global__ void __launch_bounds__(256) rmsnorm_k(const float* __restrict__ in,
    __nv_bfloat16* __restrict__ oh, __nv_bfloat16* __restrict__ ol, const float* __restrict__ w3) {
    const int row = blockIdx.x;
    const int n = row % N_;
    const int seg = n < T_ ? 0 : (n < 768 ? 1 : 2);
    const float* x = in + (size_t)row * C_;
    float v[4], s = 0.f;
    #pragma unroll
    for (int i = 0; i < 4; i++) { v[i] = x[threadIdx.x + i*256]; s += v[i]*v[i]; }
    __shared__ float red[8];
    int lane = threadIdx.x & 31, wid = threadIdx.x >> 5;
    s = warpSum(s);
    if (lane == 0) red[wid] = s;
    __syncthreads();
    if (wid == 0) { float t = (lane < 8) ? red[lane] : 0.f; t = warpSum(t); if (lane == 0) red[0] = t; }
    __syncthreads();
    float rs = rsqrtf(red[0] * (1.0f/1024.0f) + 1e-6f);
    const float* w = w3 + seg * C_;
    size_t base = (size_t)row * C_;
    #pragma unroll
    for (int i = 0; i < 4; i++) {
        int c = threadIdx.x + i*256;
        split2(w[c] * v[i] * rs, &oh[base+c], &ol[base+c]);
    }
}

// ---- q/k RMS norm + RoPE -> hi/lo (q scaled by 1/8) ----
__global__ void __launch_bounds__(256) qkrope_k(const float* __restrict__ qn_w,
    const float* __restrict__ kn_w, const int* __restrict__ pos_ids, const int* __restrict__ tpos_ids) {
    int gw = (blockIdx.x * blockDim.x + threadIdx.x) >> 5;
    int lane = threadIdx.x & 31;
    int which = gw & 1;
    int row = gw >> 1;
    if (row >= BH_ * N_) return;
    int n = row % N_;
    int seg = n < T_ ? 0 : (n < 768 ? 1 : 2);
    const float* ptr = (which ? g_k : g_q) + (size_t)row * DH;
    float x1 = ptr[lane], x2 = ptr[lane + 32];
    float rs = rsqrtf(warpSum(x1*x1 + x2*x2) * (1.0f/64.0f) + 1e-6f);
    const float* wv = (which ? kn_w : qn_w) + seg * DH;
    float y1 = wv[lane] * x1 * rs;
    float y2 = wv[lane + 32] * x2 * rs;
    int pos = (n < T_) ? tpos_ids[n] : pos_ids[n - T_];
    float ang = (float)pos * powf(10000.0f, -(float)lane * (1.0f/32.0f));
    float c = cosf(ang), s = sinf(ang);
    float o1 = y1*c - y2*s, o2 = y2*c + y1*s;
    if (!which) { o1 *= 0.125f; o2 *= 0.125f; }
    size_t b = (size_t)row * DH;
    __nv_bfloat16* dh = which ? k_h : q_h;
    __nv_bfloat16* dl = which ? k_l : q_l;
    split2(o1, &dh[b+lane], &dl[b+lane]);
    split2(o2, &dh[b+lane+32], &dl[b+lane+32]);
}

// ---- block-sparse masked softmax -> p hi/lo ----
__global__ void __launch_bounds__(256) softmax_k() {
    const int qi = blockIdx.x, z = blockIdx.y;
    const int qrow = qi >> 7;
    const int cnt = c_KCNT[qrow];
    const int tot = cnt << 7;
    size_t rb = ((size_t)z * N_ + qi) * N_;
    const int tid = threadIdx.x, lane = tid & 31, wid = tid >> 5;
    __shared__ float red[8];
    float vals[3];
    float m = -INFINITY;
    int j = 0;
    for (int i = tid; i < tot; i += 256, j++) {
        int ki = (c_KLIST[qrow][i >> 7] << 7) + (i & 127);
        float v = g_s[rb + ki];
        if (qi < T_ && ki > qi) v = -INFINITY;
        vals[j] = v; m = fmaxf(m, v);
    }
    m = warpMax(m);
    if (lane == 0) red[wid] = m;
    __syncthreads();
    if (wid == 0) { float t = (lane < 8) ? red[lane] : -INFINITY; t = warpMax(t); if (lane == 0) red[0] = t; }
    __syncthreads();
    m = red[0];
    __syncthreads();
    float s = 0.f;
    for (int i = 0; i < j; i++) {
        float e = (vals[i] == -INFINITY) ? 0.f : expf(vals[i] - m);
        vals[i] = e; s += e;
    }
    s = warpSum(s);
    if (lane == 0) red[wid] = s;
    __syncthreads();
    if (wid == 0) { float t = (lane < 8) ? red[lane] : 0.f; t = warpSum(t); if (lane == 0) red[0] = t; }
    __syncthreads();
    float rinv = 1.0f / red[0];
    j = 0;
    for (int i = tid; i < tot; i += 256, j++) {
        int ki = (c_KLIST[qrow][i >> 7] << 7) + (i & 127);
        split2(vals[j] * rinv, &p_h[rb + ki], &p_l[rb + ki]);
    }
}

// ---- silu(g)*u -> hi/lo ----
__global__ void __launch_bounds__(256) silu_k() {
    size_t i = ((size_t)blockIdx.x * 256 + threadIdx.x) * 4;
    float4 g = *(float4*)(g_g + i);
    float4 u = *(float4*)(g_u + i);
    split2(g.x / (1.f + expf(-g.x)) * u.x, &gg_h[i],   &gg_l[i]);
    split2(g.y / (1.f + expf(-g.y)) * u.y, &gg_h[i+1], &gg_l[i+1]);
    split2(g.z / (1.f + expf(-g.z)) * u.z, &gg_h[i+2], &gg_l[i+2]);
    split2(g.w / (1.f + expf(-g.w)) * u.w, &gg_h[i+3], &gg_l[i+3]);
}

// ---- host ----
extern "C" void kernel_launch(void* const* d_in, const int* in_sizes, int n_in,
                              void* d_out, int out_size) {
    (void)in_sizes; (void)n_in; (void)out_size;
    const float* x      = (const float*)d_in[0];
    const int*   pos    = (const int*)d_in[1];
    const int*   tpos   = (const int*)d_in[2];
    const float* qkv_w  = (const float*)d_in[3];
    const float* qkv_b  = (const float*)d_in[4];
    const float* proj_w = (const float*)d_in[5];
    const float* proj_b = (const float*)d_in[6];
    const float* qn_w   = (const float*)d_in[7];
    const float* kn_w   = (const float*)d_in[8];
    const float* ln1_w  = (const float*)d_in[9];
    const float* ln2_w  = (const float*)d_in[10];
    const float* gate_w = (const float*)d_in[11];
    const float* up_w   = (const float*)d_in[12];
    const float* down_w = (const float*)d_in[13];
    float* out = (float*)d_out;

    // 3-stage, BK=32: BN=128 -> 3*40960=122880;  BN=64 -> 3*30720=92160
    const int S128 = 122880, S64 = 92160;
    cudaFuncSetAttribute(mmagemm_k<128,0>, cudaFuncAttributeMaxDynamicSharedMemorySize, S128);
    cudaFuncSetAttribute(mmagemm_k<128,1>, cudaFuncAttributeMaxDynamicSharedMemorySize, S128);
    cudaFuncSetAttribute(mmagemm_k<64,2>,  cudaFuncAttributeMaxDynamicSharedMemorySize, S64);
    cudaFuncSetAttribute(mmagemm_k<64,3>,  cudaFuncAttributeMaxDynamicSharedMemorySize, S64);
    cudaFuncSetAttribute(mmagemm_k<128,7>, cudaFuncAttributeMaxDynamicSharedMemorySize, S128);
    cudaFuncSetAttribute(mmagemm_k<128,8>, cudaFuncAttributeMaxDynamicSharedMemorySize, S128);

    __nv_bfloat16 *wqh,*wql,*wph,*wpl,*wgh,*wgl,*wuh,*wul,*wdh,*wdl,*xh,*xl,*qh,*ql,*kh,*kl,*vth,*vtl,*ph,*pl,*aoh,*aol,*ggh,*ggl;
    cudaGetSymbolAddress((void**)&wqh, wqkv_h); cudaGetSymbolAddress((void**)&wql, wqkv_l);
    cudaGetSymbolAddress((void**)&wph, wprj_h); cudaGetSymbolAddress((void**)&wpl, wprj_l);
    cudaGetSymbolAddress((void**)&wgh, wgat_h); cudaGetSymbolAddress((void**)&wgl, wgat_l);
    cudaGetSymbolAddress((void**)&wuh, wup_h);  cudaGetSymbolAddress((void**)&wul, wup_l);
    cudaGetSymbolAddress((void**)&wdh, wdn_h);  cudaGetSymbolAddress((void**)&wdl, wdn_l);
    cudaGetSymbolAddress((void**)&xh, xn_h);    cudaGetSymbolAddress((void**)&xl, xn_l);
    cudaGetSymbolAddress((void**)&qh, q_h);     cudaGetSymbolAddress((void**)&ql, q_l);
    cudaGetSymbolAddress((void**)&kh, k_h);     cudaGetSymbolAddress((void**)&kl, k_l);
    cudaGetSymbolAddress((void**)&vth, vt_h);   cudaGetSymbolAddress((void**)&vtl, vt_l);
    cudaGetSymbolAddress((void**)&ph, p_h);     cudaGetSymbolAddress((void**)&pl, p_l);
    cudaGetSymbolAddress((void**)&aoh, ao_h);   cudaGetSymbolAddress((void**)&aol, ao_l);
    cudaGetSymbolAddress((void**)&ggh, gg_h);   cudaGetSymbolAddress((void**)&ggl, gg_l);
    float *fh;
    cudaGetSymbolAddress((void**)&fh, g_h);

    // weight converts
    transconv_k<<<dim3(3072/128, 1024/32, 3), 256>>>(qkv_w,  wqh, wql, 1024, 3072);
    transconv_k<<<dim3(1024/128, 1024/32, 3), 256>>>(proj_w, wph, wpl, 1024, 1024);
    transconv_k<<<dim3(4096/128, 1024/32, 3), 256>>>(gate_w, wgh, wgl, 1024, 4096);
    transconv_k<<<dim3(4096/128, 1024/32, 3), 256>>>(up_w,   wuh, wul, 1024, 4096);
    transconv_k<<<dim3(1024/128, 4096/32, 3), 256>>>(down_w, wdh, wdl, 4096, 1024);

    // ln1 -> xn
    rmsnorm_k<<<B_ * N_, 256>>>(x, xh, xl, ln1_w);
    // qkv
    mmagemm_k<128,0><<<dim3(24, 20, 1), 256, S128>>>(xh, xl, wqh, wql, qkv_b, nullptr, nullptr, 1024, 1024, 0, (long)3072*1024, 1);
    // rope (q pre-scaled by 1/8)
    qkrope_k<<<(BH_ * N_ * 2) / 8, 256>>>(qn_w, kn_w, pos, tpos);
    // scores (block-sparse: 39 of 100 tiles)
    mmagemm_k<128,1><<<dim3(39, 1, 32), 256, S128>>>(qh, ql, kh, kl, nullptr, nullptr, nullptr, 64, 64, (long)N_*DH, (long)N_*DH, 0);
    // softmax (block-sparse)
    softmax_k<<<dim3(N_, 32), 256>>>();
    // attn @ v (block-sparse K loop, longest-first order)
    mmagemm_k<64,2><<<dim3(1, 10, 32), 256, S64>>>(ph, pl, vth, vtl, nullptr, nullptr, nullptr, 1280, 1280, (long)N_*N_, (long)DH*N_, 0);
    // proj + residual -> g_h  (BN=64: 320 CTAs, balanced)
    mmagemm_k<64,3><<<dim3(16, 20, 1), 256, S64>>>(aoh, aol, wph, wpl, proj_b, x, nullptr, 1024, 1024, 0, (long)1024*1024, 1);
    // ln2 -> xn
    rmsnorm_k<<<B_ * N_, 256>>>(fh, xh, xl, ln2_w);
    // gate+up fused (1280 CTAs)
    mmagemm_k<128,8><<<dim3(64, 20, 1), 256, S128>>>(xh, xl, wgh, wgl, (const float*)wuh, (const float*)wul, nullptr, 1024, 1024, 0, (long)4096*1024, 1);
    // silu*up
    silu_k<<<(B_ * N_ * I_) / 1024, 256>>>();
    // down split-K=2 -> partials
    mmagemm_k<128,7><<<dim3(8, 20, 2), 256, S128>>>(ggh, ggl, wdh, wdl, nullptr, nullptr, nullptr, 2048, 4096, 0, (long)1024*4096, 1);
    // reduce: out = g_h + ps0 + ps1
    reduce_k<<<(B_ * N_ * C_) / 1024, 256>>>(out);
}

// round 11
// speedup vs baseline: 1.0694x; 1.0694x over previous
#include <cuda_runtime.h>
#include <cuda_bf16.h>
#include <math.h>
#include <stdint.h>

#define B_ 2
#define N_ 1280
#define C_ 1024
#define H_ 16
#define DH 64
#define I_ 4096
#define T_ 256
#define L1_ 4
#define BH_ (B_*H_)

// ---- fp32 scratch ----
__device__ float g_q[(size_t)BH_ * N_ * DH];
__device__ float g_k[(size_t)BH_ * N_ * DH];
__device__ float g_s[(size_t)BH_ * N_ * N_];
__device__ float g_h[(size_t)B_ * N_ * C_];
__device__ float g_g[(size_t)B_ * N_ * I_];
__device__ float g_u[(size_t)B_ * N_ * I_];
__device__ float g_ps[2][(size_t)B_ * N_ * C_];   // split-K partials for down
// ---- bf16 hi/lo scratch ----
__device__ __align__(16) __nv_bfloat16 xn_h[(size_t)B_*N_*C_], xn_l[(size_t)B_*N_*C_];
__device__ __align__(16) __nv_bfloat16 q_h[(size_t)BH_*N_*DH], q_l[(size_t)BH_*N_*DH];
__device__ __align__(16) __nv_bfloat16 k_h[(size_t)BH_*N_*DH], k_l[(size_t)BH_*N_*DH];
__device__ __align__(16) __nv_bfloat16 vt_h[(size_t)BH_*DH*N_], vt_l[(size_t)BH_*DH*N_];
__device__ __align__(16) __nv_bfloat16 p_h[(size_t)BH_*N_*N_], p_l[(size_t)BH_*N_*N_];
__device__ __align__(16) __nv_bfloat16 ao_h[(size_t)B_*N_*C_], ao_l[(size_t)B_*N_*C_];
__device__ __align__(16) __nv_bfloat16 gg_h[(size_t)B_*N_*I_], gg_l[(size_t)B_*N_*I_];
__device__ __align__(16) __nv_bfloat16 wqkv_h[(size_t)3*3072*1024], wqkv_l[(size_t)3*3072*1024];
__device__ __align__(16) __nv_bfloat16 wprj_h[(size_t)3*1024*1024], wprj_l[(size_t)3*1024*1024];
__device__ __align__(16) __nv_bfloat16 wgat_h[(size_t)3*4096*1024], wgat_l[(size_t)3*4096*1024];
__device__ __align__(16) __nv_bfloat16 wup_h [(size_t)3*4096*1024], wup_l [(size_t)3*4096*1024];
__device__ __align__(16) __nv_bfloat16 wdn_h [(size_t)3*1024*4096], wdn_l [(size_t)3*1024*4096];

// ---- block-sparse tables (128x128) ----
__constant__ int c_PAIRQ[39] = {0, 1,1, 2,2,2, 3,3,3,3, 4,4,4,4,4, 5,5,5,5,5,5,
                                6,6,6, 7,7,7,7, 8,8,8,8,8, 9,9,9,9,9,9};
__constant__ int c_PAIRK[39] = {0, 0,1, 0,1,2, 0,1,2,3, 0,1,2,3,4, 0,1,2,3,4,5,
                                0,1,6, 0,1,2,7, 0,1,2,3,8, 0,1,2,3,4,9};
__constant__ int c_KCNT[10] = {1,2,3,4,5,6,3,4,5,6};
__constant__ int c_KLIST[10][6] = {
    {0,0,0,0,0,0},{0,1,0,0,0,0},{0,1,2,0,0,0},{0,1,2,3,0,0},{0,1,2,3,4,0},
    {0,1,2,3,4,5},{0,1,6,0,0,0},{0,1,2,7,0,0},{0,1,2,3,8,0},{0,1,2,3,4,9}};
// attnV qrow order: descending work so long CTAs start in wave 1
__constant__ int c_QORD[10] = {5,9,4,8,3,7,2,6,1,0};

// ---- helpers ----
__device__ __forceinline__ uint32_t s2u(const void* p) {
    uint32_t a;
    asm("{ .reg .u64 t; cvta.to.shared.u64 t, %1; cvt.u32.u64 %0, t; }" : "=r"(a) : "l"(p));
    return a;
}
__device__ __forceinline__ void split2(float v, __nv_bfloat16* h, __nv_bfloat16* l) {
    __nv_bfloat16 hh = __float2bfloat16(v);
    *h = hh; *l = __float2bfloat16(v - __bfloat162float(hh));
}
__device__ __forceinline__ float warpSum(float v){
    #pragma unroll
    for (int o=16;o;o>>=1) v += __shfl_xor_sync(0xffffffffu,v,o);
    return v;
}
__device__ __forceinline__ float warpMax(float v){
    #pragma unroll
    for (int o=16;o;o>>=1) v = fmaxf(v,__shfl_xor_sync(0xffffffffu,v,o));
    return v;
}
#define LDM4(r, a) asm volatile("ldmatrix.sync.aligned.m8n8.x4.shared.b16 {%0,%1,%2,%3}, [%4];" \
    : "=r"((r)[0]),"=r"((r)[1]),"=r"((r)[2]),"=r"((r)[3]) : "r"(a))
#define LDM2(r, a) asm volatile("ldmatrix.sync.aligned.m8n8.x2.shared.b16 {%0,%1}, [%2];" \
    : "=r"((r)[0]),"=r"((r)[1]) : "r"(a))
#define MMA(d, a, b) asm volatile( \
    "mma.sync.aligned.m16n8k16.row.col.f32.bf16.bf16.f32 {%0,%1,%2,%3}, {%4,%5,%6,%7}, {%8,%9}, {%0,%1,%2,%3};" \
    : "+f"((d)[0]),"+f"((d)[1]),"+f"((d)[2]),"+f"((d)[3]) \
    : "r"((a)[0]),"r"((a)[1]),"r"((a)[2]),"r"((a)[3]),"r"((b)[0]),"r"((b)[1]))
#define CPCG() asm volatile("cp.async.commit_group;" ::: "memory")

// BK=32 tile: row stride 80B; 8 consecutive rows hit distinct 16B bank groups.
__device__ __forceinline__ void ldt32(uint32_t dstB, const __nv_bfloat16* g, int ld, int rows, int tid) {
    for (int i = tid; i < rows * 4; i += 256) {
        int r = i >> 2, q = i & 3;
        uint32_t d = dstB + (uint32_t)(r * 80 + q * 16);
        const void* s = g + (size_t)r * ld + q * 8;
        asm volatile("cp.async.cg.shared.global [%0], [%1], 16;" :: "r"(d), "l"(s));
    }
}

// ---- split-bf16 HMMA GEMM: 128 x BN block, 8 warps (2x4), BK=32, 2-stage, 1 sync/iter ----
// EPI: 0 qkv  1 scores(sparse)  2 attnV(sparse K, reordered)  3 proj  7 down split-K  8 gate+up fused
template <int BN, int EPI>
__global__ void __launch_bounds__(256) mmagemm_k(
    const __nv_bfloat16* __restrict__ Ah, const __nv_bfloat16* __restrict__ Al,
    const __nv_bfloat16* __restrict__ Bh, const __nv_bfloat16* __restrict__ Bl,
    const float* __restrict__ bias, const float* __restrict__ aux,
    float* __restrict__ Cout, int K, int ldab, long sA, long sB, int segw)
{
    constexpr int ATB = 128 * 80;
    constexpr int BTB = BN * 80;
    constexpr int SSB = 2 * ATB + 2 * BTB;
    constexpr int NW = BN / 4;
    constexpr int NT = NW / 8;
    extern __shared__ __align__(16) char smc[];
    const uint32_t sb = s2u(smc);
    const int tid = threadIdx.x, wid = tid >> 5, lane = tid & 31;
    const int wm = wid & 1, wn = wid >> 1;
    const int z = blockIdx.z;

    int brow, bcol;
    if constexpr (EPI == 1) { brow = c_PAIRQ[blockIdx.x] * 128; bcol = c_PAIRK[blockIdx.x] * 128; }
    else if constexpr (EPI == 2) { brow = c_QORD[blockIdx.y] * 128; bcol = blockIdx.x * BN; }
    else { brow = blockIdx.y * 128; bcol = blockIdx.x * BN; }

    const int* kl = nullptr;
    int nc;
    if constexpr (EPI == 2) { int qr = brow >> 7; kl = c_KLIST[qr]; nc = c_KCNT[qr] * 4; }
    else nc = K >> 5;

    int seg = 0;
    if (segw) { int n0 = brow % N_; seg = n0 < T_ ? 0 : (n0 < 768 ? 1 : 2); }
    int koff = 0;
    if constexpr (EPI == 7) koff = z * 2048;
    long zA = (EPI == 7) ? 0 : (long)z;
    const __nv_bfloat16* pAh = Ah + (size_t)zA * sA + (size_t)brow * ldab + koff;
    const __nv_bfloat16* pAl = Al + (size_t)zA * sA + (size_t)brow * ldab + koff;
    size_t boff = segw ? (size_t)seg * sB : (size_t)zA * sB;
    const __nv_bfloat16 *pBh, *pBl;
    if constexpr (EPI == 8) {
        if (bcol < I_) { pBh = Bh + boff + (size_t)bcol * ldab; pBl = Bl + boff + (size_t)bcol * ldab; }
        else {
            pBh = (const __nv_bfloat16*)bias + boff + (size_t)(bcol - I_) * ldab;
            pBl = (const __nv_bfloat16*)aux  + boff + (size_t)(bcol - I_) * ldab;
        }
    } else {
        pBh = Bh + boff + (size_t)bcol * ldab + koff;
        pBl = Bl + boff + (size_t)bcol * ldab + koff;
    }

    auto kcof = [&](int c) -> int {
        if constexpr (EPI == 2) return (kl[c >> 2] << 7) + (c & 3) * 32;
        else return c << 5;
    };
    auto load_stage = [&](int s, int kc) {
        uint32_t st = sb + (uint32_t)s * SSB;
        ldt32(st,               pAh + kc, ldab, 128, tid);
        ldt32(st + ATB,         pAl + kc, ldab, 128, tid);
        ldt32(st + 2*ATB,       pBh + kc, ldab, BN, tid);
        ldt32(st + 2*ATB + BTB, pBl + kc, ldab, BN, tid);
    };

    float acc[4][NT][4];
    #pragma unroll
    for (int i = 0; i < 4; i++)
        #pragma unroll
        for (int j = 0; j < NT; j++)
            #pragma unroll
            for (int p = 0; p < 4; p++) acc[i][j][p] = 0.f;

    load_stage(0, kcof(0));
    CPCG();

    const int lt = lane & 15;
    const uint32_t aoffH = (uint32_t)((wm * 64 + lt) * 80 + (lane >> 4) * 16);
    const uint32_t boff0 = (uint32_t)((wn * NW + (lt & 7)) * 80 + (lt >> 3) * 16);

    for (int c = 0; c < nc; c++) {
        // wait: all committed groups (latest = load c) complete.
        // sync: stage-c data visible to all threads AND all threads finished
        //       compute(c-1), so load(c+1) may overwrite buffer (c+1)&1 == (c-1)&1.
        asm volatile("cp.async.wait_group 0;" ::: "memory");
        __syncthreads();
        if (c + 1 < nc) { load_stage((c + 1) & 1, kcof(c + 1)); CPCG(); }
        uint32_t st = sb + (uint32_t)(c & 1) * SSB;
        #pragma unroll
        for (int kk = 0; kk < 2; kk++) {
            uint32_t ah[4][4], al[4][4];
            #pragma unroll
            for (int mt = 0; mt < 4; mt++) {
                uint32_t a = st + aoffH + (uint32_t)(mt * 16 * 80) + (uint32_t)(kk * 32);
                LDM4(ah[mt], a);
                LDM4(al[mt], a + ATB);
            }
            #pragma unroll
            for (int nt = 0; nt < NT; nt++) {
                uint32_t bh[2], bl[2];
                uint32_t b = st + 2*ATB + boff0 + (uint32_t)(nt * 8 * 80) + (uint32_t)(kk * 32);
                LDM2(bh, b);
                LDM2(bl, b + BTB);
                #pragma unroll
                for (int mt = 0; mt < 4; mt++) {
                    MMA(acc[mt][nt], ah[mt], bh);
                    MMA(acc[mt][nt], ah[mt], bl);
                    MMA(acc[mt][nt], al[mt], bh);
                }
            }
        }
    }

    // ---- epilogue ----
    #pragma unroll
    for (int mt = 0; mt < 4; mt++) {
        #pragma unroll
        for (int nt = 0; nt < NT; nt++) {
            #pragma unroll
            for (int p = 0; p < 2; p++) {
                int m = brow + wm * 64 + mt * 16 + (lane >> 2) + p * 8;
                #pragma unroll
                for (int j = 0; j < 2; j++) {
                    int cg = bcol + wn * NW + nt * 8 + (lane & 3) * 2 + j;
                    float v = acc[mt][nt][p * 2 + j];
                    if constexpr (EPI == 0) {
                        v += bias[seg * 3 * C_ + cg];
                        int b = m >= N_; int n = m - b * N_;
                        int which = cg >> 10, h = (cg >> 6) & 15, dd = cg & 63;
                        if (which == 0) g_q[(((size_t)(b*H_+h))*N_ + n)*DH + dd] = v;
                        else if (which == 1) g_k[(((size_t)(b*H_+h))*N_ + n)*DH + dd] = v;
                        else { size_t vi = (((size_t)(b*H_+h))*DH + dd)*N_ + n; split2(v, &vt_h[vi], &vt_l[vi]); }
                    } else if constexpr (EPI == 1) {
                        g_s[((size_t)z*N_ + m)*N_ + cg] = v;   // q pre-scaled by 1/8
                    } else if constexpr (EPI == 2) {
                        int b = z >> 4, h = z & 15;
                        size_t ai = ((size_t)(b*N_ + m))*C_ + h*DH + cg;
                        split2(v, &ao_h[ai], &ao_l[ai]);
                    } else if constexpr (EPI == 3) {
                        size_t idx = (size_t)m * C_ + cg;
                        g_h[idx] = aux[idx] + v + bias[seg * C_ + cg];
                    } else if constexpr (EPI == 7) {
                        g_ps[z][(size_t)m * C_ + cg] = v;
                    } else {   // EPI 8: gate | up
                        if (cg < I_) g_g[(size_t)m * I_ + cg] = v;
                        else         g_u[(size_t)m * I_ + cg - I_] = v;
                    }
                }
            }
        }
    }
    (void)Cout;
}

// ---- down reduce: out = g_h + ps0 + ps1 ----
__global__ void __launch_bounds__(256) reduce_k(float* __restrict__ out) {
    size_t i = ((size_t)blockIdx.x * 256 + threadIdx.x) * 4;
    float4 h = *(float4*)(g_h + i);
    float4 a = *(float4*)(&g_ps[0][i]);
    float4 b = *(float4*)(&g_ps[1][i]);
    float4 o;
    o.x = h.x + a.x + b.x; o.y = h.y + a.y + b.y;
    o.z = h.z + a.z + b.z; o.w = h.w + a.w + b.w;
    *(float4*)(out + i) = o;
}

// ---- weight transpose + hi/lo convert (vectorized): W[K,N] -> T[N,K], 32x128 tiles ----
__global__ void __launch_bounds__(256) transconv_k(const float* __restrict__ W,
    __nv_bfloat16* __restrict__ Th, __nv_bfloat16* __restrict__ Tl, int K, int N) {
    __shared__ float t[32][129];
    int sg = blockIdx.z;
    W += (size_t)sg * K * N; Th += (size_t)sg * K * N; Tl += (size_t)sg * K * N;
    int n0 = blockIdx.x * 128, k0 = blockIdx.y * 32;
    int tid = threadIdx.x;
    #pragma unroll
    for (int i = 0; i < 4; i++) {
        int id = tid + i * 256;
        int r = id >> 5, c4 = (id & 31) * 4;
        float4 v = *(const float4*)(W + (size_t)(k0 + r) * N + n0 + c4);
        t[r][c4] = v.x; t[r][c4+1] = v.y; t[r][c4+2] = v.z; t[r][c4+3] = v.w;
    }
    __syncthreads();
    int n = tid >> 1, hf = (tid & 1) * 16;
    uint32_t hb[8], lb[8];
    #pragma unroll
    for (int kk = 0; kk < 16; kk += 2) {
        float a = t[hf + kk][n], b = t[hf + kk + 1][n];
        __nv_bfloat16 ah = __float2bfloat16(a), bh = __float2bfloat16(b);
        __nv_bfloat16 alo = __float2bfloat16(a - __bfloat162float(ah));
        __nv_bfloat16 blo = __float2bfloat16(b - __bfloat162float(bh));
        hb[kk >> 1] = (uint32_t)__bfloat16_as_ushort(bh) << 16 | __bfloat16_as_ushort(ah);
        lb[kk >> 1] = (uint32_t)__bfloat16_as_ushort(blo) << 16 | __bfloat16_as_ushort(alo);
    }
    size_t o = (size_t)(n0 + n) * K + k0 + hf;
    *(uint4*)(Th + o)     = make_uint4(hb[0], hb[1], hb[2], hb[3]);
    *(uint4*)(Th + o + 8) = make_uint4(hb[4], hb[5], hb[6], hb[7]);
    *(uint4*)(Tl + o)     = make_uint4(lb[0], lb[1], lb[2], lb[3]);
    *(uint4*)(Tl + o + 8) = make_uint4(lb[4], lb[5], lb[6], lb[7]);
}

// ---- RMS norm -> hi/lo ----
__global__ void __launch_bounds__(256) rmsnorm_k(const float* __restrict__ in,
    __nv_bfloat16* __restrict__ oh, __nv_bfloat16* __restrict__ ol, const float* __restrict__ w3) {
    const int row = blockIdx.x;
    const int n = row % N_;
    const int seg = n < T_ ? 0 : (n < 768 ? 1 : 2);
    const float* x = in + (size_t)row * C_;
    float v[4], s = 0.f;
    #pragma unroll
    for (int i = 0; i < 4; i++) { v[i] = x[threadIdx.x + i*256]; s += v[i]*v[i]; }
    __shared__ float red[8];
    int lane = threadIdx.x & 31, wid = threadIdx.x >> 5;
    s = warpSum(s);
    if (lane == 0) red[wid] = s;
    __syncthreads();
    if (wid == 0) { float t = (lane < 8) ? red[lane] : 0.f; t = warpSum(t); if (lane == 0) red[0] = t; }
    __syncthreads();
    float rs = rsqrtf(red[0] * (1.0f/1024.0f) + 1e-6f);
    const float* w = w3 + seg * C_;
    size_t base = (size_t)row * C_;
    #pragma unroll
    for (int i = 0; i < 4; i++) {
        int c = threadIdx.x + i*256;
        split2(w[c] * v[i] * rs, &oh[base+c], &ol[base+c]);
    }
}

// ---- q/k RMS norm + RoPE -> hi/lo (q scaled by 1/8) ----
__global__ void __launch_bounds__(256) qkrope_k(const float* __restrict__ qn_w,
    const float* __restrict__ kn_w, const int* __restrict__ pos_ids, const int* __restrict__ tpos_ids) {
    int gw = (blockIdx.x * blockDim.x + threadIdx.x) >> 5;
    int lane = threadIdx.x & 31;
    int which = gw & 1;
    int row = gw >> 1;
    if (row >= BH_ * N_) return;
    int n = row % N_;
    int seg = n < T_ ? 0 : (n < 768 ? 1 : 2);
    const float* ptr = (which ? g_k : g_q) + (size_t)row * DH;
    float x1 = ptr[lane], x2 = ptr[lane + 32];
    float rs = rsqrtf(warpSum(x1*x1 + x2*x2) * (1.0f/64.0f) + 1e-6f);
    const float* wv = (which ? kn_w : qn_w) + seg * DH;
    float y1 = wv[lane] * x1 * rs;
    float y2 = wv[lane + 32] * x2 * rs;
    int pos = (n < T_) ? tpos_ids[n] : pos_ids[n - T_];
    float ang = (float)pos * powf(10000.0f, -(float)lane * (1.0f/32.0f));
    float c = cosf(ang), s = sinf(ang);
    float o1 = y1*c - y2*s, o2 = y2*c + y1*s;
    if (!which) { o1 *= 0.125f; o2 *= 0.125f; }
    size_t b = (size_t)row * DH;
    __nv_bfloat16* dh = which ? k_h : q_h;
    __nv_bfloat16* dl = which ? k_l : q_l;
    split2(o1, &dh[b+lane], &dl[b+lane]);
    split2(o2, &dh[b+lane+32], &dl[b+lane+32]);
}

// ---- block-sparse masked softmax -> p hi/lo ----
__global__ void __launch_bounds__(256) softmax_k() {
    const int qi = blockIdx.x, z = blockIdx.y;
    const int qrow = qi >> 7;
    const int cnt = c_KCNT[qrow];
    const int tot = cnt << 7;
    size_t rb = ((size_t)z * N_ + qi) * N_;
    const int tid = threadIdx.x, lane = tid & 31, wid = tid >> 5;
    __shared__ float red[8];
    float vals[3];
    float m = -INFINITY;
    int j = 0;
    for (int i = tid; i < tot; i += 256, j++) {
        int ki = (c_KLIST[qrow][i >> 7] << 7) + (i & 127);
        float v = g_s[rb + ki];
        if (qi < T_ && ki > qi) v = -INFINITY;
        vals[j] = v; m = fmaxf(m, v);
    }
    m = warpMax(m);
    if (lane == 0) red[wid] = m;
    __syncthreads();
    if (wid == 0) { float t = (lane < 8) ? red[lane] : -INFINITY; t = warpMax(t); if (lane == 0) red[0] = t; }
    __syncthreads();
    m = red[0];
    __syncthreads();
    float s = 0.f;
    for (int i = 0; i < j; i++) {
        float e = (vals[i] == -INFINITY) ? 0.f : expf(vals[i] - m);
        vals[i] = e; s += e;
    }
    s = warpSum(s);
    if (lane == 0) red[wid] = s;
    __syncthreads();
    if (wid == 0) { float t = (lane < 8) ? red[lane] : 0.f; t = warpSum(t); if (lane == 0) red[0] = t; }
    __syncthreads();
    float rinv = 1.0f / red[0];
    j = 0;
    for (int i = tid; i < tot; i += 256, j++) {
        int ki = (c_KLIST[qrow][i >> 7] << 7) + (i & 127);
        split2(vals[j] * rinv, &p_h[rb + ki], &p_l[rb + ki]);
    }
}

// ---- silu(g)*u -> hi/lo ----
__global__ void __launch_bounds__(256) silu_k() {
    size_t i = ((size_t)blockIdx.x * 256 + threadIdx.x) * 4;
    float4 g = *(float4*)(g_g + i);
    float4 u = *(float4*)(g_u + i);
    split2(g.x / (1.f + expf(-g.x)) * u.x, &gg_h[i],   &gg_l[i]);
    split2(g.y / (1.f + expf(-g.y)) * u.y, &gg_h[i+1], &gg_l[i+1]);
    split2(g.z / (1.f + expf(-g.z)) * u.z, &gg_h[i+2], &gg_l[i+2]);
    split2(g.w / (1.f + expf(-g.w)) * u.w, &gg_h[i+3], &gg_l[i+3]);
}

// ---- host ----
extern "C" void kernel_launch(void* const* d_in, const int* in_sizes, int n_in,
                              void* d_out, int out_size) {
    (void)in_sizes; (void)n_in; (void)out_size;
    const float* x      = (const float*)d_in[0];
    const int*   pos    = (const int*)d_in[1];
    const int*   tpos   = (const int*)d_in[2];
    const float* qkv_w  = (const float*)d_in[3];
    const float* qkv_b  = (const float*)d_in[4];
    const float* proj_w = (const float*)d_in[5];
    const float* proj_b = (const float*)d_in[6];
    const float* qn_w   = (const float*)d_in[7];
    const float* kn_w   = (const float*)d_in[8];
    const float* ln1_w  = (const float*)d_in[9];
    const float* ln2_w  = (const float*)d_in[10];
    const float* gate_w = (const float*)d_in[11];
    const float* up_w   = (const float*)d_in[12];
    const float* down_w = (const float*)d_in[13];
    float* out = (float*)d_out;

    // 2-stage, BK=32: BN=128 -> 2*40960=81920 (2 CTAs/SM);  BN=64 -> 2*30720=61440
    const int S128 = 81920, S64 = 61440;
    cudaFuncSetAttribute(mmagemm_k<128,0>, cudaFuncAttributeMaxDynamicSharedMemorySize, S128);
    cudaFuncSetAttribute(mmagemm_k<128,1>, cudaFuncAttributeMaxDynamicSharedMemorySize, S128);
    cudaFuncSetAttribute(mmagemm_k<64,2>,  cudaFuncAttributeMaxDynamicSharedMemorySize, S64);
    cudaFuncSetAttribute(mmagemm_k<64,3>,  cudaFuncAttributeMaxDynamicSharedMemorySize, S64);
    cudaFuncSetAttribute(mmagemm_k<128,7>, cudaFuncAttributeMaxDynamicSharedMemorySize, S128);
    cudaFuncSetAttribute(mmagemm_k<128,8>, cudaFuncAttributeMaxDynamicSharedMemorySize, S128);

    __nv_bfloat16 *wqh,*wql,*wph,*wpl,*wgh,*wgl,*wuh,*wul,*wdh,*wdl,*xh,*xl,*qh,*ql,*kh,*kl,*vth,*vtl,*ph,*pl,*aoh,*aol,*ggh,*ggl;
    cudaGetSymbolAddress((void**)&wqh, wqkv_h); cudaGetSymbolAddress((void**)&wql, wqkv_l);
    cudaGetSymbolAddress((void**)&wph, wprj_h); cudaGetSymbolAddress((void**)&wpl, wprj_l);
    cudaGetSymbolAddress((void**)&wgh, wgat_h); cudaGetSymbolAddress((void**)&wgl, wgat_l);
    cudaGetSymbolAddress((void**)&wuh, wup_h);  cudaGetSymbolAddress((void**)&wul, wup_l);
    cudaGetSymbolAddress((void**)&wdh, wdn_h);  cudaGetSymbolAddress((void**)&wdl, wdn_l);
    cudaGetSymbolAddress((void**)&xh, xn_h);    cudaGetSymbolAddress((void**)&xl, xn_l);
    cudaGetSymbolAddress((void**)&qh, q_h);     cudaGetSymbolAddress((void**)&ql, q_l);
    cudaGetSymbolAddress((void**)&kh, k_h);     cudaGetSymbolAddress((void**)&kl, k_l);
    cudaGetSymbolAddress((void**)&vth, vt_h);   cudaGetSymbolAddress((void**)&vtl, vt_l);
    cudaGetSymbolAddress((void**)&ph, p_h);     cudaGetSymbolAddress((void**)&pl, p_l);
    cudaGetSymbolAddress((void**)&aoh, ao_h);   cudaGetSymbolAddress((void**)&aol, ao_l);
    cudaGetSymbolAddress((void**)&ggh, gg_h);   cudaGetSymbolAddress((void**)&ggl, gg_l);
    float *fh;
    cudaGetSymbolAddress((void**)&fh, g_h);

    // weight converts
    transconv_k<<<dim3(3072/128, 1024/32, 3), 256>>>(qkv_w,  wqh, wql, 1024, 3072);
    transconv_k<<<dim3(1024/128, 1024/32, 3), 256>>>(proj_w, wph, wpl, 1024, 1024);
    transconv_k<<<dim3(4096/128, 1024/32, 3), 256>>>(gate_w, wgh, wgl, 1024, 4096);
    transconv_k<<<dim3(4096/128, 1024/32, 3), 256>>>(up_w,   wuh, wul, 1024, 4096);
    transconv_k<<<dim3(1024/128, 4096/32, 3), 256>>>(down_w, wdh, wdl, 4096, 1024);

    // ln1 -> xn
    rmsnorm_k<<<B_ * N_, 256>>>(x, xh, xl, ln1_w);
    // qkv
    mmagemm_k<128,0><<<dim3(24, 20, 1), 256, S128>>>(xh, xl, wqh, wql, qkv_b, nullptr, nullptr, 1024, 1024, 0, (long)3072*1024, 1);
    // rope (q pre-scaled by 1/8)
    qkrope_k<<<(BH_ * N_ * 2) / 8, 256>>>(qn_w, kn_w, pos, tpos);
    // scores (block-sparse: 39 of 100 tiles)
    mmagemm_k<128,1><<<dim3(39, 1, 32), 256, S128>>>(qh, ql, kh, kl, nullptr, nullptr, nullptr, 64, 64, (long)N_*DH, (long)N_*DH, 0);
    // softmax (block-sparse)
    softmax_k<<<dim3(N_, 32), 256>>>();
    // attn @ v (block-sparse K loop, longest-first order)
    mmagemm_k<64,2><<<dim3(1, 10, 32), 256, S64>>>(ph, pl, vth, vtl, nullptr, nullptr, nullptr, 1280, 1280, (long)N_*N_, (long)DH*N_, 0);
    // proj + residual -> g_h  (BN=64: 320 CTAs, balanced)
    mmagemm_k<64,3><<<dim3(16, 20, 1), 256, S64>>>(aoh, aol, wph, wpl, proj_b, x, nullptr, 1024, 1024, 0, (long)1024*1024, 1);
    // ln2 -> xn
    rmsnorm_k<<<B_ * N_, 256>>>(fh, xh, xl, ln2_w);
    // gate+up fused (1280 CTAs)
    mmagemm_k<128,8><<<dim3(64, 20, 1), 256, S128>>>(xh, xl, wgh, wgl, (const float*)wuh, (const float*)wul, nullptr, 1024, 1024, 0, (long)4096*1024, 1);
    // silu*up
    silu_k<<<(B_ * N_ * I_) / 1024, 256>>>();
    // down split-K=2 -> partials
    mmagemm_k<128,7><<<dim3(8, 20, 2), 256, S128>>>(ggh, ggl, wdh, wdl, nullptr, nullptr, nullptr, 2048, 4096, 0, (long)1024*4096, 1);
    // reduce: out = g_h + ps0 + ps1
    reduce_k<<<(B_ * N_ * C_) / 1024, 256>>>(out);
}

// round 12
// speedup vs baseline: 1.2063x; 1.1281x over previous
#include <cuda_runtime.h>
#include <cuda_bf16.h>
#include <math.h>
#include <stdint.h>

#define B_ 2
#define N_ 1280
#define C_ 1024
#define H_ 16
#define DH 64
#define I_ 4096
#define T_ 256
#define BH_ (B_*H_)

// ---- fp32 scratch ----
__device__ float g_q[(size_t)BH_ * N_ * DH];
__device__ float g_k[(size_t)BH_ * N_ * DH];
__device__ float g_h[(size_t)B_ * N_ * C_];
__device__ float g_g[(size_t)B_ * N_ * I_];
__device__ float g_u[(size_t)B_ * N_ * I_];
__device__ float g_ps[2][(size_t)B_ * N_ * C_];
// ---- bf16 hi/lo scratch ----
__device__ __align__(16) __nv_bfloat16 xn_h[(size_t)B_*N_*C_], xn_l[(size_t)B_*N_*C_];
__device__ __align__(16) __nv_bfloat16 q_h[(size_t)BH_*N_*DH], q_l[(size_t)BH_*N_*DH];
__device__ __align__(16) __nv_bfloat16 k_h[(size_t)BH_*N_*DH], k_l[(size_t)BH_*N_*DH];
__device__ __align__(16) __nv_bfloat16 vt_h[(size_t)BH_*DH*N_], vt_l[(size_t)BH_*DH*N_];
__device__ __align__(16) __nv_bfloat16 ao_h[(size_t)B_*N_*C_], ao_l[(size_t)B_*N_*C_];
__device__ __align__(16) __nv_bfloat16 gg_h[(size_t)B_*N_*I_], gg_l[(size_t)B_*N_*I_];
__device__ __align__(16) __nv_bfloat16 wqkv_h[(size_t)3*3072*1024], wqkv_l[(size_t)3*3072*1024];
__device__ __align__(16) __nv_bfloat16 wprj_h[(size_t)3*1024*1024], wprj_l[(size_t)3*1024*1024];
__device__ __align__(16) __nv_bfloat16 wgat_h[(size_t)3*4096*1024], wgat_l[(size_t)3*4096*1024];
__device__ __align__(16) __nv_bfloat16 wup_h [(size_t)3*4096*1024], wup_l [(size_t)3*4096*1024];
__device__ __align__(16) __nv_bfloat16 wdn_h [(size_t)3*1024*4096], wdn_l [(size_t)3*1024*4096];

// ---- block-sparse tables (128x128 granularity) ----
__constant__ int c_KCNT[10] = {1,2,3,4,5,6,3,4,5,6};
__constant__ int c_KLIST[10][6] = {
    {0,0,0,0,0,0},{0,1,0,0,0,0},{0,1,2,0,0,0},{0,1,2,3,0,0},{0,1,2,3,4,0},
    {0,1,2,3,4,5},{0,1,6,0,0,0},{0,1,2,7,0,0},{0,1,2,3,8,0},{0,1,2,3,4,9}};
__constant__ int c_QORD[10] = {5,9,4,8,3,7,2,6,1,0};  // longest-first

// ---- helpers ----
__device__ __forceinline__ uint32_t s2u(const void* p) {
    uint32_t a;
    asm("{ .reg .u64 t; cvta.to.shared.u64 t, %1; cvt.u32.u64 %0, t; }" : "=r"(a) : "l"(p));
    return a;
}
__device__ __forceinline__ void split2(float v, __nv_bfloat16* h, __nv_bfloat16* l) {
    __nv_bfloat16 hh = __float2bfloat16(v);
    *h = hh; *l = __float2bfloat16(v - __bfloat162float(hh));
}
__device__ __forceinline__ uint32_t pack2(float a, float b) {
    return (uint32_t)__bfloat16_as_ushort(__float2bfloat16(b)) << 16 |
           __bfloat16_as_ushort(__float2bfloat16(a));
}
__device__ __forceinline__ float warpSum(float v){
    #pragma unroll
    for (int o=16;o;o>>=1) v += __shfl_xor_sync(0xffffffffu,v,o);
    return v;
}
__device__ __forceinline__ float warpMax(float v){
    #pragma unroll
    for (int o=16;o;o>>=1) v = fmaxf(v,__shfl_xor_sync(0xffffffffu,v,o));
    return v;
}
#define LDM4(r, a) asm volatile("ldmatrix.sync.aligned.m8n8.x4.shared.b16 {%0,%1,%2,%3}, [%4];" \
    : "=r"((r)[0]),"=r"((r)[1]),"=r"((r)[2]),"=r"((r)[3]) : "r"(a))
#define LDM2(r, a) asm volatile("ldmatrix.sync.aligned.m8n8.x2.shared.b16 {%0,%1}, [%2];" \
    : "=r"((r)[0]),"=r"((r)[1]) : "r"(a))
#define MMA(d, a, b) asm volatile( \
    "mma.sync.aligned.m16n8k16.row.col.f32.bf16.bf16.f32 {%0,%1,%2,%3}, {%4,%5,%6,%7}, {%8,%9}, {%0,%1,%2,%3};" \
    : "+f"((d)[0]),"+f"((d)[1]),"+f"((d)[2]),"+f"((d)[3]) \
    : "r"((a)[0]),"r"((a)[1]),"r"((a)[2]),"r"((a)[3]),"r"((b)[0]),"r"((b)[1]))
#define CPCG() asm volatile("cp.async.commit_group;" ::: "memory")

// generic 16B-chunk tile loader: rows x (chunks*16B), padded row stride
__device__ __forceinline__ void ldtile(uint32_t dstB, const __nv_bfloat16* g, int ldelem,
                                       int rows, int chunks, int stride, int tid) {
    int tot = rows * chunks;
    for (int i = tid; i < tot; i += 256) {
        int r = i / chunks, q = i - r * chunks;
        uint32_t d = dstB + (uint32_t)(r * stride + q * 16);
        const void* s = g + (size_t)r * ldelem + q * 8;
        asm volatile("cp.async.cg.shared.global [%0], [%1], 16;" :: "r"(d), "l"(s));
    }
}
// BK=32 tile for GEMMs: row stride 80B
__device__ __forceinline__ void ldt32(uint32_t dstB, const __nv_bfloat16* g, int ld, int rows, int tid) {
    for (int i = tid; i < rows * 4; i += 256) {
        int r = i >> 2, q = i & 3;
        uint32_t d = dstB + (uint32_t)(r * 80 + q * 16);
        const void* s = g + (size_t)r * ld + q * 8;
        asm volatile("cp.async.cg.shared.global [%0], [%1], 16;" :: "r"(d), "l"(s));
    }
}

// ======== fused flash attention: S=QK^T, mask, online softmax, O=PV ========
// grid (32 z, 10 qrow-slot), 256 thr, 8 warps (2x4). smem offsets:
#define FQ0 0
#define FQ1 18432
#define FK0 36864
#define FK1 55296
#define FV0 73728
#define FV1 91136
#define FP0 108544
#define FP1 143360
#define FRA 178176
#define FRB 180224
#define FSM 182272
__global__ void __launch_bounds__(256) flash_k() {
    extern __shared__ __align__(16) char smc[];
    const uint32_t sb = s2u(smc);
    const int tid = threadIdx.x, wid = tid >> 5, lane = tid & 31;
    const int wm = wid & 1, wn = wid >> 1;
    const int lt = lane & 15;
    const int z = blockIdx.x;
    const int qr = c_QORD[blockIdx.y];
    const int cnt = c_KCNT[qr];
    const int bq = z >> 4, hq = z & 15;
    float* redA = (float*)(smc + FRA);
    float* redB = (float*)(smc + FRB);

    // Q tile (once)
    ldtile(sb + FQ0, q_h + ((size_t)z * N_ + qr * 128) * DH, DH, 128, 8, 144, tid);
    ldtile(sb + FQ1, q_l + ((size_t)z * N_ + qr * 128) * DH, DH, 128, 8, 144, tid);

    float m_run[4][2], l_run[4][2], oacc[4][2][4];
    #pragma unroll
    for (int mt = 0; mt < 4; mt++)
        #pragma unroll
        for (int p = 0; p < 2; p++) {
            m_run[mt][p] = -INFINITY; l_run[mt][p] = 0.f;
            oacc[mt][0][p*2] = oacc[mt][0][p*2+1] = 0.f;
            oacc[mt][1][p*2] = oacc[mt][1][p*2+1] = 0.f;
        }

    const uint32_t aQ0 = (uint32_t)((wm*64 + lt) * 144 + (lane >> 4) * 16);
    const uint32_t bK0 = (uint32_t)((wn*32 + (lt & 7)) * 144 + ((lt >> 3) & 1) * 16);
    const uint32_t bV0 = (uint32_t)((wn*16 + (lt & 7)) * 272 + ((lt >> 3) & 1) * 16);
    const uint32_t aP0 = (uint32_t)((wm*64 + lt) * 272 + (lane >> 4) * 16);

    for (int j = 0; j < cnt; j++) {
        const int kb = c_KLIST[qr][j];
        const int kv0 = kb << 7;
        ldtile(sb + FK0, k_h + ((size_t)z * N_ + kv0) * DH, DH, 128, 8, 144, tid);
        ldtile(sb + FK1, k_l + ((size_t)z * N_ + kv0) * DH, DH, 128, 8, 144, tid);
        ldtile(sb + FV0, vt_h + (size_t)z * DH * N_ + kv0, N_, 64, 16, 272, tid);
        ldtile(sb + FV1, vt_l + (size_t)z * DH * N_ + kv0, N_, 64, 16, 272, tid);
        CPCG();
        asm volatile("cp.async.wait_group 0;" ::: "memory");
        __syncthreads();

        // ---- S = Q K^T (3-term split) ----
        float sacc[4][4][4];
        #pragma unroll
        for (int a = 0; a < 4; a++)
            #pragma unroll
            for (int b = 0; b < 4; b++)
                #pragma unroll
                for (int c = 0; c < 4; c++) sacc[a][b][c] = 0.f;
        #pragma unroll
        for (int kk = 0; kk < 4; kk++) {
            uint32_t qh4[4][4], ql4[4][4];
            #pragma unroll
            for (int mt = 0; mt < 4; mt++) {
                uint32_t a = sb + aQ0 + (uint32_t)(mt * 16 * 144 + kk * 32);
                LDM4(qh4[mt], a + FQ0);
                LDM4(ql4[mt], a + FQ1);
            }
            #pragma unroll
            for (int nt = 0; nt < 4; nt++) {
                uint32_t kh2[2], kl2[2];
                uint32_t b = sb + bK0 + (uint32_t)(nt * 8 * 144 + kk * 32);
                LDM2(kh2, b + FK0);
                LDM2(kl2, b + FK1);
                #pragma unroll
                for (int mt = 0; mt < 4; mt++) {
                    MMA(sacc[mt][nt], qh4[mt], kh2);
                    MMA(sacc[mt][nt], qh4[mt], kl2);
                    MMA(sacc[mt][nt], ql4[mt], kh2);
                }
            }
        }
        // ---- mask (text diagonal blocks only) ----
        if (qr < 2 && kb == qr) {
            #pragma unroll
            for (int mt = 0; mt < 4; mt++)
                #pragma unroll
                for (int p = 0; p < 2; p++) {
                    int qi = qr*128 + wm*64 + mt*16 + (lane >> 2) + p*8;
                    #pragma unroll
                    for (int nt = 0; nt < 4; nt++)
                        #pragma unroll
                        for (int jj = 0; jj < 2; jj++) {
                            int ki = kv0 + wn*32 + nt*8 + (lane & 3)*2 + jj;
                            if (ki > qi) sacc[mt][nt][p*2+jj] = -INFINITY;
                        }
                }
        }
        // ---- row max (cross-warp) ----
        #pragma unroll
        for (int mt = 0; mt < 4; mt++)
            #pragma unroll
            for (int p = 0; p < 2; p++) {
                float v = sacc[mt][0][p*2];
                #pragma unroll
                for (int nt = 0; nt < 4; nt++) {
                    v = fmaxf(v, sacc[mt][nt][p*2]);
                    v = fmaxf(v, sacc[mt][nt][p*2+1]);
                }
                v = fmaxf(v, __shfl_xor_sync(0xffffffffu, v, 1));
                v = fmaxf(v, __shfl_xor_sync(0xffffffffu, v, 2));
                if ((lane & 3) == 0)
                    redA[wn*128 + wm*64 + mt*16 + (lane >> 2) + p*8] = v;
            }
        __syncthreads();
        float m_new[4][2], alpha[4][2];
        #pragma unroll
        for (int mt = 0; mt < 4; mt++)
            #pragma unroll
            for (int p = 0; p < 2; p++) {
                int rr = wm*64 + mt*16 + (lane >> 2) + p*8;
                float bm = fmaxf(fmaxf(redA[rr], redA[128+rr]), fmaxf(redA[256+rr], redA[384+rr]));
                float mn = fmaxf(m_run[mt][p], bm);
                alpha[mt][p] = __expf(m_run[mt][p] - mn);
                m_run[mt][p] = mn;
                m_new[mt][p] = mn;
                l_run[mt][p] *= alpha[mt][p];
                oacc[mt][0][p*2]   *= alpha[mt][p]; oacc[mt][0][p*2+1] *= alpha[mt][p];
                oacc[mt][1][p*2]   *= alpha[mt][p]; oacc[mt][1][p*2+1] *= alpha[mt][p];
            }
        // ---- exp, row sums, write P hi/lo to smem ----
        #pragma unroll
        for (int mt = 0; mt < 4; mt++)
            #pragma unroll
            for (int p = 0; p < 2; p++) {
                int rr = wm*64 + mt*16 + (lane >> 2) + p*8;
                float rs = 0.f;
                #pragma unroll
                for (int nt = 0; nt < 4; nt++) {
                    float e0 = __expf(sacc[mt][nt][p*2]   - m_new[mt][p]);
                    float e1 = __expf(sacc[mt][nt][p*2+1] - m_new[mt][p]);
                    rs += e0 + e1;
                    int cc = wn*32 + nt*8 + (lane & 3)*2;
                    uint32_t off = (uint32_t)(rr * 272 + cc * 2);
                    __nv_bfloat16 h0 = __float2bfloat16(e0), h1 = __float2bfloat16(e1);
                    *(uint32_t*)(smc + FP0 + off) =
                        (uint32_t)__bfloat16_as_ushort(h1) << 16 | __bfloat16_as_ushort(h0);
                    *(uint32_t*)(smc + FP1 + off) =
                        pack2(e0 - __bfloat162float(h0), e1 - __bfloat162float(h1));
                }
                rs += __shfl_xor_sync(0xffffffffu, rs, 1);
                rs += __shfl_xor_sync(0xffffffffu, rs, 2);
                if ((lane & 3) == 0) redB[wn*128 + rr] = rs;
            }
        __syncthreads();
        #pragma unroll
        for (int mt = 0; mt < 4; mt++)
            #pragma unroll
            for (int p = 0; p < 2; p++) {
                int rr = wm*64 + mt*16 + (lane >> 2) + p*8;
                l_run[mt][p] += redB[rr] + redB[128+rr] + redB[256+rr] + redB[384+rr];
            }
        // ---- O += P V (3-term split) ----
        #pragma unroll
        for (int kk = 0; kk < 8; kk++) {
            uint32_t ph4[4][4], pl4[4][4];
            #pragma unroll
            for (int mt = 0; mt < 4; mt++) {
                uint32_t a = sb + aP0 + (uint32_t)(mt * 16 * 272 + kk * 32);
                LDM4(ph4[mt], a + FP0);
                LDM4(pl4[mt], a + FP1);
            }
            #pragma unroll
            for (int nt = 0; nt < 2; nt++) {
                uint32_t vh2[2], vl2[2];
                uint32_t b = sb + bV0 + (uint32_t)(nt * 8 * 272 + kk * 32);
                LDM2(vh2, b + FV0);
                LDM2(vl2, b + FV1);
                #pragma unroll
                for (int mt = 0; mt < 4; mt++) {
                    MMA(oacc[mt][nt], ph4[mt], vh2);
                    MMA(oacc[mt][nt], ph4[mt], vl2);
                    MMA(oacc[mt][nt], pl4[mt], vh2);
                }
            }
        }
        __syncthreads();
    }
    // ---- epilogue: O/l -> ao hi/lo ----
    #pragma unroll
    for (int mt = 0; mt < 4; mt++)
        #pragma unroll
        for (int p = 0; p < 2; p++) {
            float rinv = 1.0f / l_run[mt][p];
            int mg = qr*128 + wm*64 + mt*16 + (lane >> 2) + p*8;
            #pragma unroll
            for (int nt = 0; nt < 2; nt++)
                #pragma unroll
                for (int jj = 0; jj < 2; jj++) {
                    int dh = wn*16 + nt*8 + (lane & 3)*2 + jj;
                    size_t ai = ((size_t)(bq * N_ + mg)) * C_ + hq * DH + dh;
                    split2(oacc[mt][nt][p*2+jj] * rinv, &ao_h[ai], &ao_l[ai]);
                }
        }
}

// ---- split-bf16 HMMA GEMM: 128 x BN block, 8 warps (2x4), BK=32, 2-stage ----
// EPI: 0 qkv  3 proj  7 down split-K  8 gate+up fused
template <int BN, int EPI>
__global__ void __launch_bounds__(256) mmagemm_k(
    const __nv_bfloat16* __restrict__ Ah, const __nv_bfloat16* __restrict__ Al,
    const __nv_bfloat16* __restrict__ Bh, const __nv_bfloat16* __restrict__ Bl,
    const float* __restrict__ bias, const float* __restrict__ aux,
    float* __restrict__ Cout, int K, int ldab, long sA, long sB, int segw)
{
    constexpr int ATB = 128 * 80;
    constexpr int BTB = BN * 80;
    constexpr int SSB = 2 * ATB + 2 * BTB;
    constexpr int NW = BN / 4;
    constexpr int NT = NW / 8;
    extern __shared__ __align__(16) char smc[];
    const uint32_t sb = s2u(smc);
    const int tid = threadIdx.x, wid = tid >> 5, lane = tid & 31;
    const int wm = wid & 1, wn = wid >> 1;
    const int z = blockIdx.z;
    const int brow = blockIdx.y * 128, bcol = blockIdx.x * BN;
    const int nc = K >> 5;

    int seg = 0;
    if (segw) { int n0 = brow % N_; seg = n0 < T_ ? 0 : (n0 < 768 ? 1 : 2); }
    int koff = 0;
    if constexpr (EPI == 7) koff = z * 2048;
    long zA = (EPI == 7) ? 0 : (long)z;
    const __nv_bfloat16* pAh = Ah + (size_t)zA * sA + (size_t)brow * ldab + koff;
    const __nv_bfloat16* pAl = Al + (size_t)zA * sA + (size_t)brow * ldab + koff;
    size_t boff = segw ? (size_t)seg * sB : (size_t)zA * sB;
    const __nv_bfloat16 *pBh, *pBl;
    if constexpr (EPI == 8) {
        if (bcol < I_) { pBh = Bh + boff + (size_t)bcol * ldab; pBl = Bl + boff + (size_t)bcol * ldab; }
        else {
            pBh = (const __nv_bfloat16*)bias + boff + (size_t)(bcol - I_) * ldab;
            pBl = (const __nv_bfloat16*)aux  + boff + (size_t)(bcol - I_) * ldab;
        }
    } else {
        pBh = Bh + boff + (size_t)bcol * ldab + koff;
        pBl = Bl + boff + (size_t)bcol * ldab + koff;
    }

    auto load_stage = [&](int s, int kc) {
        uint32_t st = sb + (uint32_t)s * SSB;
        ldt32(st,               pAh + kc, ldab, 128, tid);
        ldt32(st + ATB,         pAl + kc, ldab, 128, tid);
        ldt32(st + 2*ATB,       pBh + kc, ldab, BN, tid);
        ldt32(st + 2*ATB + BTB, pBl + kc, ldab, BN, tid);
    };

    float acc[4][NT][4];
    #pragma unroll
    for (int i = 0; i < 4; i++)
        #pragma unroll
        for (int j = 0; j < NT; j++)
            #pragma unroll
            for (int p = 0; p < 4; p++) acc[i][j][p] = 0.f;

    load_stage(0, 0);
    CPCG();

    const int lt = lane & 15;
    const uint32_t aoffH = (uint32_t)((wm * 64 + lt) * 80 + (lane >> 4) * 16);
    const uint32_t boff0 = (uint32_t)((wn * NW + (lt & 7)) * 80 + (lt >> 3) * 16);

    for (int c = 0; c < nc; c++) {
        asm volatile("cp.async.wait_group 0;" ::: "memory");
        __syncthreads();
        if (c + 1 < nc) { load_stage((c + 1) & 1, (c + 1) << 5); CPCG(); }
        uint32_t st = sb + (uint32_t)(c & 1) * SSB;
        #pragma unroll
        for (int kk = 0; kk < 2; kk++) {
            uint32_t ah[4][4], al[4][4];
            #pragma unroll
            for (int mt = 0; mt < 4; mt++) {
                uint32_t a = st + aoffH + (uint32_t)(mt * 16 * 80) + (uint32_t)(kk * 32);
                LDM4(ah[mt], a);
                LDM4(al[mt], a + ATB);
            }
            #pragma unroll
            for (int nt = 0; nt < NT; nt++) {
                uint32_t bh[2], bl[2];
                uint32_t b = st + 2*ATB + boff0 + (uint32_t)(nt * 8 * 80) + (uint32_t)(kk * 32);
                LDM2(bh, b);
                LDM2(bl, b + BTB);
                #pragma unroll
                for (int mt = 0; mt < 4; mt++) {
                    MMA(acc[mt][nt], ah[mt], bh);
                    MMA(acc[mt][nt], ah[mt], bl);
                    MMA(acc[mt][nt], al[mt], bh);
                }
            }
        }
    }

    #pragma unroll
    for (int mt = 0; mt < 4; mt++) {
        #pragma unroll
        for (int nt = 0; nt < NT; nt++) {
            #pragma unroll
            for (int p = 0; p < 2; p++) {
                int m = brow + wm * 64 + mt * 16 + (lane >> 2) + p * 8;
                #pragma unroll
                for (int j = 0; j < 2; j++) {
                    int cg = bcol + wn * NW + nt * 8 + (lane & 3) * 2 + j;
                    float v = acc[mt][nt][p * 2 + j];
                    if constexpr (EPI == 0) {
                        v += bias[seg * 3 * C_ + cg];
                        int b = m >= N_; int n = m - b * N_;
                        int which = cg >> 10, h = (cg >> 6) & 15, dd = cg & 63;
                        if (which == 0) g_q[(((size_t)(b*H_+h))*N_ + n)*DH + dd] = v;
                        else if (which == 1) g_k[(((size_t)(b*H_+h))*N_ + n)*DH + dd] = v;
                        else { size_t vi = (((size_t)(b*H_+h))*DH + dd)*N_ + n; split2(v, &vt_h[vi], &vt_l[vi]); }
                    } else if constexpr (EPI == 3) {
                        size_t idx = (size_t)m * C_ + cg;
                        g_h[idx] = aux[idx] + v + bias[seg * C_ + cg];
                    } else if constexpr (EPI == 7) {
                        g_ps[z][(size_t)m * C_ + cg] = v;
                    } else {
                        if (cg < I_) g_g[(size_t)m * I_ + cg] = v;
                        else         g_u[(size_t)m * I_ + cg - I_] = v;
                    }
                }
            }
        }
    }
    (void)Cout;
}

// ---- down reduce: out = g_h + ps0 + ps1 ----
__global__ void __launch_bounds__(256) reduce_k(float* __restrict__ out) {
    size_t i = ((size_t)blockIdx.x * 256 + threadIdx.x) * 4;
    float4 h = *(float4*)(g_h + i);
    float4 a = *(float4*)(&g_ps[0][i]);
    float4 b = *(float4*)(&g_ps[1][i]);
    float4 o;
    o.x = h.x + a.x + b.x; o.y = h.y + a.y + b.y;
    o.z = h.z + a.z + b.z; o.w = h.w + a.w + b.w;
    *(float4*)(out + i) = o;
}

// ---- weight transpose + hi/lo convert: W[K,N] -> T[N,K], 32x128 tiles ----
__global__ void __launch_bounds__(256) transconv_k(const float* __restrict__ W,
    __nv_bfloat16* __restrict__ Th, __nv_bfloat16* __restrict__ Tl, int K, int N) {
    __shared__ float t[32][129];
    int sg = blockIdx.z;
    W += (size_t)sg * K * N; Th += (size_t)sg * K * N; Tl += (size_t)sg * K * N;
    int n0 = blockIdx.x * 128, k0 = blockIdx.y * 32;
    int tid = threadIdx.x;
    #pragma unroll
    for (int i = 0; i < 4; i++) {
        int id = tid + i * 256;
        int r = id >> 5, c4 = (id & 31) * 4;
        float4 v = *(const float4*)(W + (size_t)(k0 + r) * N + n0 + c4);
        t[r][c4] = v.x; t[r][c4+1] = v.y; t[r][c4+2] = v.z; t[r][c4+3] = v.w;
    }
    __syncthreads();
    int n = tid >> 1, hf = (tid & 1) * 16;
    uint32_t hb[8], lb[8];
    #pragma unroll
    for (int kk = 0; kk < 16; kk += 2) {
        float a = t[hf + kk][n], b = t[hf + kk + 1][n];
        __nv_bfloat16 ah = __float2bfloat16(a), bh = __float2bfloat16(b);
        hb[kk >> 1] = (uint32_t)__bfloat16_as_ushort(bh) << 16 | __bfloat16_as_ushort(ah);
        lb[kk >> 1] = pack2(a - __bfloat162float(ah), b - __bfloat162float(bh));
    }
    size_t o = (size_t)(n0 + n) * K + k0 + hf;
    *(uint4*)(Th + o)     = make_uint4(hb[0], hb[1], hb[2], hb[3]);
    *(uint4*)(Th + o + 8) = make_uint4(hb[4], hb[5], hb[6], hb[7]);
    *(uint4*)(Tl + o)     = make_uint4(lb[0], lb[1], lb[2], lb[3]);
    *(uint4*)(Tl + o + 8) = make_uint4(lb[4], lb[5], lb[6], lb[7]);
}

// ---- RMS norm -> hi/lo ----
__global__ void __launch_bounds__(256) rmsnorm_k(const float* __restrict__ in,
    __nv_bfloat16* __restrict__ oh, __nv_bfloat16* __restrict__ ol, const float* __restrict__ w3) {
    const int row = blockIdx.x;
    const int n = row % N_;
    const int seg = n < T_ ? 0 : (n < 768 ? 1 : 2);
    const float* x = in + (size_t)row * C_;
    float v[4], s = 0.f;
    #pragma unroll
    for (int i = 0; i < 4; i++) { v[i] = x[threadIdx.x + i*256]; s += v[i]*v[i]; }
    __shared__ float red[8];
    int lane = threadIdx.x & 31, wid = threadIdx.x >> 5;
    s = warpSum(s);
    if (lane == 0) red[wid] = s;
    __syncthreads();
    if (wid == 0) { float t = (lane < 8) ? red[lane] : 0.f; t = warpSum(t); if (lane == 0) red[0] = t; }
    __syncthreads();
    float rs = rsqrtf(red[0] * (1.0f/1024.0f) + 1e-6f);
    const float* w = w3 + seg * C_;
    size_t base = (size_t)row * C_;
    #pragma unroll
    for (int i = 0; i < 4; i++) {
        int c = threadIdx.x + i*256;
        split2(w[c] * v[i] * rs, &oh[base+c], &ol[base+c]);
    }
}

// ---- q/k RMS norm + RoPE -> hi/lo (q scaled by 1/8) ----
__global__ void __launch_bounds__(256) qkrope_k(const float* __restrict__ qn_w,
    const float* __restrict__ kn_w, const int* __restrict__ pos_ids, const int* __restrict__ tpos_ids) {
    int gw = (blockIdx.x * blockDim.x + threadIdx.x) >> 5;
    int lane = threadIdx.x & 31;
    int which = gw & 1;
    int row = gw >> 1;
    if (row >= BH_ * N_) return;
    int n = row % N_;
    int seg = n < T_ ? 0 : (n < 768 ? 1 : 2);
    const float* ptr = (which ? g_k : g_q) + (size_t)row * DH;
    float x1 = ptr[lane], x2 = ptr[lane + 32];
    float rs = rsqrtf(warpSum(x1*x1 + x2*x2) * (1.0f/64.0f) + 1e-6f);
    const float* wv = (which ? kn_w : qn_w) + seg * DH;
    float y1 = wv[lane] * x1 * rs;
    float y2 = wv[lane + 32] * x2 * rs;
    int pos = (n < T_) ? tpos_ids[n] : pos_ids[n - T_];
    float ang = (float)pos * powf(10000.0f, -(float)lane * (1.0f/32.0f));
    float c = cosf(ang), s = sinf(ang);
    float o1 = y1*c - y2*s, o2 = y2*c + y1*s;
    if (!which) { o1 *= 0.125f; o2 *= 0.125f; }
    size_t b = (size_t)row * DH;
    __nv_bfloat16* dh = which ? k_h : q_h;
    __nv_bfloat16* dl = which ? k_l : q_l;
    split2(o1, &dh[b+lane], &dl[b+lane]);
    split2(o2, &dh[b+lane+32], &dl[b+lane+32]);
}

// ---- silu(g)*u -> hi/lo ----
__global__ void __launch_bounds__(256) silu_k() {
    size_t i = ((size_t)blockIdx.x * 256 + threadIdx.x) * 4;
    float4 g = *(float4*)(g_g + i);
    float4 u = *(float4*)(g_u + i);
    split2(g.x / (1.f + expf(-g.x)) * u.x, &gg_h[i],   &gg_l[i]);
    split2(g.y / (1.f + expf(-g.y)) * u.y, &gg_h[i+1], &gg_l[i+1]);
    split2(g.z / (1.f + expf(-g.z)) * u.z, &gg_h[i+2], &gg_l[i+2]);
    split2(g.w / (1.f + expf(-g.w)) * u.w, &gg_h[i+3], &gg_l[i+3]);
}

// ---- host ----
extern "C" void kernel_launch(void* const* d_in, const int* in_sizes, int n_in,
                              void* d_out, int out_size) {
    (void)in_sizes; (void)n_in; (void)out_size;
    const float* x      = (const float*)d_in[0];
    const int*   pos    = (const int*)d_in[1];
    const int*   tpos   = (const int*)d_in[2];
    const float* qkv_w  = (const float*)d_in[3];
    const float* qkv_b  = (const float*)d_in[4];
    const float* proj_w = (const float*)d_in[5];
    const float* proj_b = (const float*)d_in[6];
    const float* qn_w   = (const float*)d_in[7];
    const float* kn_w   = (const float*)d_in[8];
    const float* ln1_w  = (const float*)d_in[9];
    const float* ln2_w  = (const float*)d_in[10];
    const float* gate_w = (const float*)d_in[11];
    const float* up_w   = (const float*)d_in[12];
    const float* down_w = (const float*)d_in[13];
    float* out = (float*)d_out;

    const int S128 = 81920, S64 = 61440;
    cudaFuncSetAttribute(mmagemm_k<128,0>, cudaFuncAttributeMaxDynamicSharedMemorySize, S128);
    cudaFuncSetAttribute(mmagemm_k<64,3>,  cudaFuncAttributeMaxDynamicSharedMemorySize, S64);
    cudaFuncSetAttribute(mmagemm_k<128,7>, cudaFuncAttributeMaxDynamicSharedMemorySize, S128);
    cudaFuncSetAttribute(mmagemm_k<128,8>, cudaFuncAttributeMaxDynamicSharedMemorySize, S128);
    cudaFuncSetAttribute(flash_k, cudaFuncAttributeMaxDynamicSharedMemorySize, FSM);

    __nv_bfloat16 *wqh,*wql,*wph,*wpl,*wgh,*wgl,*wuh,*wul,*wdh,*wdl,*xh,*xl,*aoh,*aol,*ggh,*ggl;
    cudaGetSymbolAddress((void**)&wqh, wqkv_h); cudaGetSymbolAddress((void**)&wql, wqkv_l);
    cudaGetSymbolAddress((void**)&wph, wprj_h); cudaGetSymbolAddress((void**)&wpl, wprj_l);
    cudaGetSymbolAddress((void**)&wgh, wgat_h); cudaGetSymbolAddress((void**)&wgl, wgat_l);
    cudaGetSymbolAddress((void**)&wuh, wup_h);  cudaGetSymbolAddress((void**)&wul, wup_l);
    cudaGetSymbolAddress((void**)&wdh, wdn_h);  cudaGetSymbolAddress((void**)&wdl, wdn_l);
    cudaGetSymbolAddress((void**)&xh, xn_h);    cudaGetSymbolAddress((void**)&xl, xn_l);
    cudaGetSymbolAddress((void**)&aoh, ao_h);   cudaGetSymbolAddress((void**)&aol, ao_l);
    cudaGetSymbolAddress((void**)&ggh, gg_h);   cudaGetSymbolAddress((void**)&ggl, gg_l);
    float *fh;
    cudaGetSymbolAddress((void**)&fh, g_h);

    transconv_k<<<dim3(3072/128, 1024/32, 3), 256>>>(qkv_w,  wqh, wql, 1024, 3072);
    transconv_k<<<dim3(1024/128, 1024/32, 3), 256>>>(proj_w, wph, wpl, 1024, 1024);
    transconv_k<<<dim3(4096/128, 1024/32, 3), 256>>>(gate_w, wgh, wgl, 1024, 4096);
    transconv_k<<<dim3(4096/128, 1024/32, 3), 256>>>(up_w,   wuh, wul, 1024, 4096);
    transconv_k<<<dim3(1024/128, 4096/32, 3), 256>>>(down_w, wdh, wdl, 4096, 1024);

    rmsnorm_k<<<B_ * N_, 256>>>(x, xh, xl, ln1_w);
    mmagemm_k<128,0><<<dim3(24, 20, 1), 256, S128>>>(xh, xl, wqh, wql, qkv_b, nullptr, nullptr, 1024, 1024, 0, (long)3072*1024, 1);
    qkrope_k<<<(BH_ * N_ * 2) / 8, 256>>>(qn_w, kn_w, pos, tpos);
    // fused attention: scores + mask + softmax + PV -> ao
    flash_k<<<dim3(32, 10), 256, FSM>>>();
    mmagemm_k<64,3><<<dim3(16, 20, 1), 256, S64>>>(aoh, aol, wph, wpl, proj_b, x, nullptr, 1024, 1024, 0, (long)1024*1024, 1);
    rmsnorm_k<<<B_ * N_, 256>>>(fh, xh, xl, ln2_w);
    mmagemm_k<128,8><<<dim3(64, 20, 1), 256, S128>>>(xh, xl, wgh, wgl, (const float*)wuh, (const float*)wul, nullptr, 1024, 1024, 0, (long)4096*1024, 1);
    silu_k<<<(B_ * N_ * I_) / 1024, 256>>>();
    mmagemm_k<128,7><<<dim3(8, 20, 2), 256, S128>>>(ggh, ggl, wdh, wdl, nullptr, nullptr, nullptr, 2048, 4096, 0, (long)1024*4096, 1);
    reduce_k<<<(B_ * N_ * C_) / 1024, 256>>>(out);
}

// round 13
// speedup vs baseline: 1.2065x; 1.0002x over previous
#include <cuda_runtime.h>
#include <cuda_bf16.h>
#include <math.h>
#include <stdint.h>

#define B_ 2
#define N_ 1280
#define C_ 1024
#define H_ 16
#define DH 64
#define I_ 4096
#define T_ 256
#define BH_ (B_*H_)

// ---- fp32 scratch ----
__device__ float g_q[(size_t)BH_ * N_ * DH];
__device__ float g_k[(size_t)BH_ * N_ * DH];
__device__ float g_h[(size_t)B_ * N_ * C_];
__device__ float g_g[(size_t)B_ * N_ * I_];
__device__ float g_u[(size_t)B_ * N_ * I_];
__device__ float g_ps[2][(size_t)B_ * N_ * C_];
// ---- bf16 hi/lo scratch ----
__device__ __align__(16) __nv_bfloat16 xn_h[(size_t)B_*N_*C_], xn_l[(size_t)B_*N_*C_];
__device__ __align__(16) __nv_bfloat16 q_h[(size_t)BH_*N_*DH], q_l[(size_t)BH_*N_*DH];
__device__ __align__(16) __nv_bfloat16 k_h[(size_t)BH_*N_*DH], k_l[(size_t)BH_*N_*DH];
__device__ __align__(16) __nv_bfloat16 vt_h[(size_t)BH_*DH*N_], vt_l[(size_t)BH_*DH*N_];
__device__ __align__(16) __nv_bfloat16 ao_h[(size_t)B_*N_*C_], ao_l[(size_t)B_*N_*C_];
__device__ __align__(16) __nv_bfloat16 gg_h[(size_t)B_*N_*I_], gg_l[(size_t)B_*N_*I_];
__device__ __align__(16) __nv_bfloat16 wqkv_h[(size_t)3*3072*1024], wqkv_l[(size_t)3*3072*1024];
__device__ __align__(16) __nv_bfloat16 wprj_h[(size_t)3*1024*1024], wprj_l[(size_t)3*1024*1024];
__device__ __align__(16) __nv_bfloat16 wgat_h[(size_t)3*4096*1024], wgat_l[(size_t)3*4096*1024];
__device__ __align__(16) __nv_bfloat16 wup_h [(size_t)3*4096*1024], wup_l [(size_t)3*4096*1024];
__device__ __align__(16) __nv_bfloat16 wdn_h [(size_t)3*1024*4096], wdn_l [(size_t)3*1024*4096];

// ---- block-sparse tables (128x128 granularity) ----
__constant__ int c_KCNT[10] = {1,2,3,4,5,6,3,4,5,6};
__constant__ int c_KLIST[10][6] = {
    {0,0,0,0,0,0},{0,1,0,0,0,0},{0,1,2,0,0,0},{0,1,2,3,0,0},{0,1,2,3,4,0},
    {0,1,2,3,4,5},{0,1,6,0,0,0},{0,1,2,7,0,0},{0,1,2,3,8,0},{0,1,2,3,4,9}};
__constant__ int c_QORD[10] = {5,9,4,8,3,7,2,6,1,0};  // longest-first

// ---- helpers ----
__device__ __forceinline__ uint32_t s2u(const void* p) {
    uint32_t a;
    asm("{ .reg .u64 t; cvta.to.shared.u64 t, %1; cvt.u32.u64 %0, t; }" : "=r"(a) : "l"(p));
    return a;
}
__device__ __forceinline__ void split2(float v, __nv_bfloat16* h, __nv_bfloat16* l) {
    __nv_bfloat16 hh = __float2bfloat16(v);
    *h = hh; *l = __float2bfloat16(v - __bfloat162float(hh));
}
__device__ __forceinline__ uint32_t pack2(float a, float b) {
    return (uint32_t)__bfloat16_as_ushort(__float2bfloat16(b)) << 16 |
           __bfloat16_as_ushort(__float2bfloat16(a));
}
__device__ __forceinline__ float warpSum(float v){
    #pragma unroll
    for (int o=16;o;o>>=1) v += __shfl_xor_sync(0xffffffffu,v,o);
    return v;
}
__device__ __forceinline__ float warpMax(float v){
    #pragma unroll
    for (int o=16;o;o>>=1) v = fmaxf(v,__shfl_xor_sync(0xffffffffu,v,o));
    return v;
}
#define LDM4(r, a) asm volatile("ldmatrix.sync.aligned.m8n8.x4.shared.b16 {%0,%1,%2,%3}, [%4];" \
    : "=r"((r)[0]),"=r"((r)[1]),"=r"((r)[2]),"=r"((r)[3]) : "r"(a))
#define LDM2(r, a) asm volatile("ldmatrix.sync.aligned.m8n8.x2.shared.b16 {%0,%1}, [%2];" \
    : "=r"((r)[0]),"=r"((r)[1]) : "r"(a))
#define MMA(d, a, b) asm volatile( \
    "mma.sync.aligned.m16n8k16.row.col.f32.bf16.bf16.f32 {%0,%1,%2,%3}, {%4,%5,%6,%7}, {%8,%9}, {%0,%1,%2,%3};" \
    : "+f"((d)[0]),"+f"((d)[1]),"+f"((d)[2]),"+f"((d)[3]) \
    : "r"((a)[0]),"r"((a)[1]),"r"((a)[2]),"r"((a)[3]),"r"((b)[0]),"r"((b)[1]))
#define CPCG() asm volatile("cp.async.commit_group;" ::: "memory")

// generic 16B-chunk tile loader: rows x (chunks*16B), padded row stride
__device__ __forceinline__ void ldtile(uint32_t dstB, const __nv_bfloat16* g, int ldelem,
                                       int rows, int chunks, int stride, int tid) {
    int tot = rows * chunks;
    for (int i = tid; i < tot; i += 256) {
        int r = i / chunks, q = i - r * chunks;
        uint32_t d = dstB + (uint32_t)(r * stride + q * 16);
        const void* s = g + (size_t)r * ldelem + q * 8;
        asm volatile("cp.async.cg.shared.global [%0], [%1], 16;" :: "r"(d), "l"(s));
    }
}
// BK=32 tile for GEMMs: row stride 80B
__device__ __forceinline__ void ldt32(uint32_t dstB, const __nv_bfloat16* g, int ld, int rows, int tid) {
    for (int i = tid; i < rows * 4; i += 256) {
        int r = i >> 2, q = i & 3;
        uint32_t d = dstB + (uint32_t)(r * 80 + q * 16);
        const void* s = g + (size_t)r * ld + q * 8;
        asm volatile("cp.async.cg.shared.global [%0], [%1], 16;" :: "r"(d), "l"(s));
    }
}

// ======== fused flash attention: S=QK^T, mask, online softmax, O=PV ========
// grid (32 z, 10 qrow-slot), 256 thr, 8 warps (2x4). smem offsets:
#define FQ0 0
#define FQ1 18432
#define FK0 36864
#define FK1 55296
#define FV0 73728
#define FV1 91136
#define FP0 108544
#define FP1 143360
#define FRA 178176
#define FRB 180224
#define FSM 182272
__global__ void __launch_bounds__(256) flash_k() {
    extern __shared__ __align__(16) char smc[];
    const uint32_t sb = s2u(smc);
    const int tid = threadIdx.x, wid = tid >> 5, lane = tid & 31;
    const int wm = wid & 1, wn = wid >> 1;
    const int lt = lane & 15;
    const int z = blockIdx.x;
    const int qr = c_QORD[blockIdx.y];
    const int cnt = c_KCNT[qr];
    const int bq = z >> 4, hq = z & 15;
    float* redA = (float*)(smc + FRA);
    float* redB = (float*)(smc + FRB);

    // Q tile (once)
    ldtile(sb + FQ0, q_h + ((size_t)z * N_ + qr * 128) * DH, DH, 128, 8, 144, tid);
    ldtile(sb + FQ1, q_l + ((size_t)z * N_ + qr * 128) * DH, DH, 128, 8, 144, tid);

    float m_run[4][2], l_run[4][2], oacc[4][2][4];
    #pragma unroll
    for (int mt = 0; mt < 4; mt++)
        #pragma unroll
        for (int p = 0; p < 2; p++) {
            m_run[mt][p] = -INFINITY; l_run[mt][p] = 0.f;
            oacc[mt][0][p*2] = oacc[mt][0][p*2+1] = 0.f;
            oacc[mt][1][p*2] = oacc[mt][1][p*2+1] = 0.f;
        }

    const uint32_t aQ0 = (uint32_t)((wm*64 + lt) * 144 + (lane >> 4) * 16);
    const uint32_t bK0 = (uint32_t)((wn*32 + (lt & 7)) * 144 + ((lt >> 3) & 1) * 16);
    const uint32_t bV0 = (uint32_t)((wn*16 + (lt & 7)) * 272 + ((lt >> 3) & 1) * 16);
    const uint32_t aP0 = (uint32_t)((wm*64 + lt) * 272 + (lane >> 4) * 16);

    for (int j = 0; j < cnt; j++) {
        const int kb = c_KLIST[qr][j];
        const int kv0 = kb << 7;
        ldtile(sb + FK0, k_h + ((size_t)z * N_ + kv0) * DH, DH, 128, 8, 144, tid);
        ldtile(sb + FK1, k_l + ((size_t)z * N_ + kv0) * DH, DH, 128, 8, 144, tid);
        ldtile(sb + FV0, vt_h + (size_t)z * DH * N_ + kv0, N_, 64, 16, 272, tid);
        ldtile(sb + FV1, vt_l + (size_t)z * DH * N_ + kv0, N_, 64, 16, 272, tid);
        CPCG();
        asm volatile("cp.async.wait_group 0;" ::: "memory");
        __syncthreads();

        // ---- S = Q K^T (3-term split) ----
        float sacc[4][4][4];
        #pragma unroll
        for (int a = 0; a < 4; a++)
            #pragma unroll
            for (int b = 0; b < 4; b++)
                #pragma unroll
                for (int c = 0; c < 4; c++) sacc[a][b][c] = 0.f;
        #pragma unroll
        for (int kk = 0; kk < 4; kk++) {
            uint32_t qh4[4][4], ql4[4][4];
            #pragma unroll
            for (int mt = 0; mt < 4; mt++) {
                uint32_t a = sb + aQ0 + (uint32_t)(mt * 16 * 144 + kk * 32);
                LDM4(qh4[mt], a + FQ0);
                LDM4(ql4[mt], a + FQ1);
            }
            #pragma unroll
            for (int nt = 0; nt < 4; nt++) {
                uint32_t kh2[2], kl2[2];
                uint32_t b = sb + bK0 + (uint32_t)(nt * 8 * 144 + kk * 32);
                LDM2(kh2, b + FK0);
                LDM2(kl2, b + FK1);
                #pragma unroll
                for (int mt = 0; mt < 4; mt++) {
                    MMA(sacc[mt][nt], qh4[mt], kh2);
                    MMA(sacc[mt][nt], qh4[mt], kl2);
                    MMA(sacc[mt][nt], ql4[mt], kh2);
                }
            }
        }
        // ---- mask (text diagonal blocks only) ----
        if (qr < 2 && kb == qr) {
            #pragma unroll
            for (int mt = 0; mt < 4; mt++)
                #pragma unroll
                for (int p = 0; p < 2; p++) {
                    int qi = qr*128 + wm*64 + mt*16 + (lane >> 2) + p*8;
                    #pragma unroll
                    for (int nt = 0; nt < 4; nt++)
                        #pragma unroll
                        for (int jj = 0; jj < 2; jj++) {
                            int ki = kv0 + wn*32 + nt*8 + (lane & 3)*2 + jj;
                            if (ki > qi) sacc[mt][nt][p*2+jj] = -INFINITY;
                        }
                }
        }
        // ---- row max (cross-warp) ----
        #pragma unroll
        for (int mt = 0; mt < 4; mt++)
            #pragma unroll
            for (int p = 0; p < 2; p++) {
                float v = sacc[mt][0][p*2];
                #pragma unroll
                for (int nt = 0; nt < 4; nt++) {
                    v = fmaxf(v, sacc[mt][nt][p*2]);
                    v = fmaxf(v, sacc[mt][nt][p*2+1]);
                }
                v = fmaxf(v, __shfl_xor_sync(0xffffffffu, v, 1));
                v = fmaxf(v, __shfl_xor_sync(0xffffffffu, v, 2));
                if ((lane & 3) == 0)
                    redA[wn*128 + wm*64 + mt*16 + (lane >> 2) + p*8] = v;
            }
        __syncthreads();
        float m_new[4][2], alpha[4][2];
        #pragma unroll
        for (int mt = 0; mt < 4; mt++)
            #pragma unroll
            for (int p = 0; p < 2; p++) {
                int rr = wm*64 + mt*16 + (lane >> 2) + p*8;
                float bm = fmaxf(fmaxf(redA[rr], redA[128+rr]), fmaxf(redA[256+rr], redA[384+rr]));
                float mn = fmaxf(m_run[mt][p], bm);
                alpha[mt][p] = __expf(m_run[mt][p] - mn);
                m_run[mt][p] = mn;
                m_new[mt][p] = mn;
                l_run[mt][p] *= alpha[mt][p];
                oacc[mt][0][p*2]   *= alpha[mt][p]; oacc[mt][0][p*2+1] *= alpha[mt][p];
                oacc[mt][1][p*2]   *= alpha[mt][p]; oacc[mt][1][p*2+1] *= alpha[mt][p];
            }
        // ---- exp, row sums, write P hi/lo to smem ----
        #pragma unroll
        for (int mt = 0; mt < 4; mt++)
            #pragma unroll
            for (int p = 0; p < 2; p++) {
                int rr = wm*64 + mt*16 + (lane >> 2) + p*8;
                float rs = 0.f;
                #pragma unroll
                for (int nt = 0; nt < 4; nt++) {
                    float e0 = __expf(sacc[mt][nt][p*2]   - m_new[mt][p]);
                    float e1 = __expf(sacc[mt][nt][p*2+1] - m_new[mt][p]);
                    rs += e0 + e1;
                    int cc = wn*32 + nt*8 + (lane & 3)*2;
                    uint32_t off = (uint32_t)(rr * 272 + cc * 2);
                    __nv_bfloat16 h0 = __float2bfloat16(e0), h1 = __float2bfloat16(e1);
                    *(uint32_t*)(smc + FP0 + off) =
                        (uint32_t)__bfloat16_as_ushort(h1) << 16 | __bfloat16_as_ushort(h0);
                    *(uint32_t*)(smc + FP1 + off) =
                        pack2(e0 - __bfloat162float(h0), e1 - __bfloat162float(h1));
                }
                rs += __shfl_xor_sync(0xffffffffu, rs, 1);
                rs += __shfl_xor_sync(0xffffffffu, rs, 2);
                if ((lane & 3) == 0) redB[wn*128 + rr] = rs;
            }
        __syncthreads();
        #pragma unroll
        for (int mt = 0; mt < 4; mt++)
            #pragma unroll
            for (int p = 0; p < 2; p++) {
                int rr = wm*64 + mt*16 + (lane >> 2) + p*8;
                l_run[mt][p] += redB[rr] + redB[128+rr] + redB[256+rr] + redB[384+rr];
            }
        // ---- O += P V (3-term split) ----
        #pragma unroll
        for (int kk = 0; kk < 8; kk++) {
            uint32_t ph4[4][4], pl4[4][4];
            #pragma unroll
            for (int mt = 0; mt < 4; mt++) {
                uint32_t a = sb + aP0 + (uint32_t)(mt * 16 * 272 + kk * 32);
                LDM4(ph4[mt], a + FP0);
                LDM4(pl4[mt], a + FP1);
            }
            #pragma unroll
            for (int nt = 0; nt < 2; nt++) {
                uint32_t vh2[2], vl2[2];
                uint32_t b = sb + bV0 + (uint32_t)(nt * 8 * 272 + kk * 32);
                LDM2(vh2, b + FV0);
                LDM2(vl2, b + FV1);
                #pragma unroll
                for (int mt = 0; mt < 4; mt++) {
                    MMA(oacc[mt][nt], ph4[mt], vh2);
                    MMA(oacc[mt][nt], ph4[mt], vl2);
                    MMA(oacc[mt][nt], pl4[mt], vh2);
                }
            }
        }
        __syncthreads();
    }
    // ---- epilogue: O/l -> ao hi/lo ----
    #pragma unroll
    for (int mt = 0; mt < 4; mt++)
        #pragma unroll
        for (int p = 0; p < 2; p++) {
            float rinv = 1.0f / l_run[mt][p];
            int mg = qr*128 + wm*64 + mt*16 + (lane >> 2) + p*8;
            #pragma unroll
            for (int nt = 0; nt < 2; nt++)
                #pragma unroll
                for (int jj = 0; jj < 2; jj++) {
                    int dh = wn*16 + nt*8 + (lane & 3)*2 + jj;
                    size_t ai = ((size_t)(bq * N_ + mg)) * C_ + hq * DH + dh;
                    split2(oacc[mt][nt][p*2+jj] * rinv, &ao_h[ai], &ao_l[ai]);
                }
        }
}

// ---- split-bf16 HMMA GEMM: 128 x BN block, 8 warps (2x4), BK=32, 2-stage ----
// EPI: 0 qkv  3 proj  7 down split-K  8 gate+up fused
template <int BN, int EPI>
__global__ void __launch_bounds__(256) mmagemm_k(
    const __nv_bfloat16* __restrict__ Ah, const __nv_bfloat16* __restrict__ Al,
    const __nv_bfloat16* __restrict__ Bh, const __nv_bfloat16* __restrict__ Bl,
    const float* __restrict__ bias, const float* __restrict__ aux,
    float* __restrict__ Cout, int K, int ldab, long sA, long sB, int segw)
{
    constexpr int ATB = 128 * 80;
    constexpr int BTB = BN * 80;
    constexpr int SSB = 2 * ATB + 2 * BTB;
    constexpr int NW = BN / 4;
    constexpr int NT = NW / 8;
    extern __shared__ __align__(16) char smc[];
    const uint32_t sb = s2u(smc);
    const int tid = threadIdx.x, wid = tid >> 5, lane = tid & 31;
    const int wm = wid & 1, wn = wid >> 1;
    const int z = blockIdx.z;
    const int brow = blockIdx.y * 128, bcol = blockIdx.x * BN;
    const int nc = K >> 5;

    int seg = 0;
    if (segw) { int n0 = brow % N_; seg = n0 < T_ ? 0 : (n0 < 768 ? 1 : 2); }
    int koff = 0;
    if constexpr (EPI == 7) koff = z * 2048;
    long zA = (EPI == 7) ? 0 : (long)z;
    const __nv_bfloat16* pAh = Ah + (size_t)zA * sA + (size_t)brow * ldab + koff;
    const __nv_bfloat16* pAl = Al + (size_t)zA * sA + (size_t)brow * ldab + koff;
    size_t boff = segw ? (size_t)seg * sB : (size_t)zA * sB;
    const __nv_bfloat16 *pBh, *pBl;
    if constexpr (EPI == 8) {
        if (bcol < I_) { pBh = Bh + boff + (size_t)bcol * ldab; pBl = Bl + boff + (size_t)bcol * ldab; }
        else {
            pBh = (const __nv_bfloat16*)bias + boff + (size_t)(bcol - I_) * ldab;
            pBl = (const __nv_bfloat16*)aux  + boff + (size_t)(bcol - I_) * ldab;
        }
    } else {
        pBh = Bh + boff + (size_t)bcol * ldab + koff;
        pBl = Bl + boff + (size_t)bcol * ldab + koff;
    }

    auto load_stage = [&](int s, int kc) {
        uint32_t st = sb + (uint32_t)s * SSB;
        ldt32(st,               pAh + kc, ldab, 128, tid);
        ldt32(st + ATB,         pAl + kc, ldab, 128, tid);
        ldt32(st + 2*ATB,       pBh + kc, ldab, BN, tid);
        ldt32(st + 2*ATB + BTB, pBl + kc, ldab, BN, tid);
    };

    float acc[4][NT][4];
    #pragma unroll
    for (int i = 0; i < 4; i++)
        #pragma unroll
        for (int j = 0; j < NT; j++)
            #pragma unroll
            for (int p = 0; p < 4; p++) acc[i][j][p] = 0.f;

    load_stage(0, 0);
    CPCG();

    const int lt = lane & 15;
    const uint32_t aoffH = (uint32_t)((wm * 64 + lt) * 80 + (lane >> 4) * 16);
    const uint32_t boff0 = (uint32_t)((wn * NW + (lt & 7)) * 80 + (lt >> 3) * 16);

    for (int c = 0; c < nc; c++) {
        asm volatile("cp.async.wait_group 0;" ::: "memory");
        __syncthreads();
        if (c + 1 < nc) { load_stage((c + 1) & 1, (c + 1) << 5); CPCG(); }
        uint32_t st = sb + (uint32_t)(c & 1) * SSB;
        #pragma unroll
        for (int kk = 0; kk < 2; kk++) {
            uint32_t ah[4][4], al[4][4];
            #pragma unroll
            for (int mt = 0; mt < 4; mt++) {
                uint32_t a = st + aoffH + (uint32_t)(mt * 16 * 80) + (uint32_t)(kk * 32);
                LDM4(ah[mt], a);
                LDM4(al[mt], a + ATB);
            }
            #pragma unroll
            for (int nt = 0; nt < NT; nt++) {
                uint32_t bh[2], bl[2];
                uint32_t b = st + 2*ATB + boff0 + (uint32_t)(nt * 8 * 80) + (uint32_t)(kk * 32);
                LDM2(bh, b);
                LDM2(bl, b + BTB);
                #pragma unroll
                for (int mt = 0; mt < 4; mt++) {
                    MMA(acc[mt][nt], ah[mt], bh);
                    MMA(acc[mt][nt], ah[mt], bl);
                    MMA(acc[mt][nt], al[mt], bh);
                }
            }
        }
    }

    #pragma unroll
    for (int mt = 0; mt < 4; mt++) {
        #pragma unroll
        for (int nt = 0; nt < NT; nt++) {
            #pragma unroll
            for (int p = 0; p < 2; p++) {
                int m = brow + wm * 64 + mt * 16 + (lane >> 2) + p * 8;
                #pragma unroll
                for (int j = 0; j < 2; j++) {
                    int cg = bcol + wn * NW + nt * 8 + (lane & 3) * 2 + j;
                    float v = acc[mt][nt][p * 2 + j];
                    if constexpr (EPI == 0) {
                        v += bias[seg * 3 * C_ + cg];
                        int b = m >= N_; int n = m - b * N_;
                        int which = cg >> 10, h = (cg >> 6) & 15, dd = cg & 63;
                        if (which == 0) g_q[(((size_t)(b*H_+h))*N_ + n)*DH + dd] = v;
                        else if (which == 1) g_k[(((size_t)(b*H_+h))*N_ + n)*DH + dd] = v;
                        else { size_t vi = (((size_t)(b*H_+h))*DH + dd)*N_ + n; split2(v, &vt_h[vi], &vt_l[vi]); }
                    } else if constexpr (EPI == 3) {
                        size_t idx = (size_t)m * C_ + cg;
                        g_h[idx] = aux[idx] + v + bias[seg * C_ + cg];
                    } else if constexpr (EPI == 7) {
                        g_ps[z][(size_t)m * C_ + cg] = v;
                    } else {
                        if (cg < I_) g_g[(size_t)m * I_ + cg] = v;
                        else         g_u[(size_t)m * I_ + cg - I_] = v;
                    }
                }
            }
        }
    }
    (void)Cout;
}

// ---- down reduce: out = g_h + ps0 + ps1 ----
__global__ void __launch_bounds__(256) reduce_k(float* __restrict__ out) {
    size_t i = ((size_t)blockIdx.x * 256 + threadIdx.x) * 4;
    float4 h = *(float4*)(g_h + i);
    float4 a = *(float4*)(&g_ps[0][i]);
    float4 b = *(float4*)(&g_ps[1][i]);
    float4 o;
    o.x = h.x + a.x + b.x; o.y = h.y + a.y + b.y;
    o.z = h.z + a.z + b.z; o.w = h.w + a.w + b.w;
    *(float4*)(out + i) = o;
}

// ---- weight transpose + hi/lo convert: W[K,N] -> T[N,K], 32x128 tiles ----
__global__ void __launch_bounds__(256) transconv_k(const float* __restrict__ W,
    __nv_bfloat16* __restrict__ Th, __nv_bfloat16* __restrict__ Tl, int K, int N) {
    __shared__ float t[32][129];
    int sg = blockIdx.z;
    W += (size_t)sg * K * N; Th += (size_t)sg * K * N; Tl += (size_t)sg * K * N;
    int n0 = blockIdx.x * 128, k0 = blockIdx.y * 32;
    int tid = threadIdx.x;
    #pragma unroll
    for (int i = 0; i < 4; i++) {
        int id = tid + i * 256;
        int r = id >> 5, c4 = (id & 31) * 4;
        float4 v = *(const float4*)(W + (size_t)(k0 + r) * N + n0 + c4);
        t[r][c4] = v.x; t[r][c4+1] = v.y; t[r][c4+2] = v.z; t[r][c4+3] = v.w;
    }
    __syncthreads();
    int n = tid >> 1, hf = (tid & 1) * 16;
    uint32_t hb[8], lb[8];
    #pragma unroll
    for (int kk = 0; kk < 16; kk += 2) {
        float a = t[hf + kk][n], b = t[hf + kk + 1][n];
        __nv_bfloat16 ah = __float2bfloat16(a), bh = __float2bfloat16(b);
        hb[kk >> 1] = (uint32_t)__bfloat16_as_ushort(bh) << 16 | __bfloat16_as_ushort(ah);
        lb[kk >> 1] = pack2(a - __bfloat162float(ah), b - __bfloat162float(bh));
    }
    size_t o = (size_t)(n0 + n) * K + k0 + hf;
    *(uint4*)(Th + o)     = make_uint4(hb[0], hb[1], hb[2], hb[3]);
    *(uint4*)(Th + o + 8) = make_uint4(hb[4], hb[5], hb[6], hb[7]);
    *(uint4*)(Tl + o)     = make_uint4(lb[0], lb[1], lb[2], lb[3]);
    *(uint4*)(Tl + o + 8) = make_uint4(lb[4], lb[5], lb[6], lb[7]);
}

// ---- RMS norm -> hi/lo ----
__global__ void __launch_bounds__(256) rmsnorm_k(const float* __restrict__ in,
    __nv_bfloat16* __restrict__ oh, __nv_bfloat16* __restrict__ ol, const float* __restrict__ w3) {
    const int row = blockIdx.x;
    const int n = row % N_;
    const int seg = n < T_ ? 0 : (n < 768 ? 1 : 2);
    const float* x = in + (size_t)row * C_;
    float v[4], s = 0.f;
    #pragma unroll
    for (int i = 0; i < 4; i++) { v[i] = x[threadIdx.x + i*256]; s += v[i]*v[i]; }
    __shared__ float red[8];
    int lane = threadIdx.x & 31, wid = threadIdx.x >> 5;
    s = warpSum(s);
    if (lane == 0) red[wid] = s;
    __syncthreads();
    if (wid == 0) { float t = (lane < 8) ? red[lane] : 0.f; t = warpSum(t); if (lane == 0) red[0] = t; }
    __syncthreads();
    float rs = rsqrtf(red[0] * (1.0f/1024.0f) + 1e-6f);
    const float* w = w3 + seg * C_;
    size_t base = (size_t)row * C_;
    #pragma unroll
    for (int i = 0; i < 4; i++) {
        int c = threadIdx.x + i*256;
        split2(w[c] * v[i] * rs, &oh[base+c], &ol[base+c]);
    }
}

// ---- q/k RMS norm + RoPE -> hi/lo (q scaled by 1/8) ----
__global__ void __launch_bounds__(256) qkrope_k(const float* __restrict__ qn_w,
    const float* __restrict__ kn_w, const int* __restrict__ pos_ids, const int* __restrict__ tpos_ids) {
    int gw = (blockIdx.x * blockDim.x + threadIdx.x) >> 5;
    int lane = threadIdx.x & 31;
    int which = gw & 1;
    int row = gw >> 1;
    if (row >= BH_ * N_) return;
    int n = row % N_;
    int seg = n < T_ ? 0 : (n < 768 ? 1 : 2);
    const float* ptr = (which ? g_k : g_q) + (size_t)row * DH;
    float x1 = ptr[lane], x2 = ptr[lane + 32];
    float rs = rsqrtf(warpSum(x1*x1 + x2*x2) * (1.0f/64.0f) + 1e-6f);
    const float* wv = (which ? kn_w : qn_w) + seg * DH;
    float y1 = wv[lane] * x1 * rs;
    float y2 = wv[lane + 32] * x2 * rs;
    int pos = (n < T_) ? tpos_ids[n] : pos_ids[n - T_];
    float ang = (float)pos * powf(10000.0f, -(float)lane * (1.0f/32.0f));
    float c = cosf(ang), s = sinf(ang);
    float o1 = y1*c - y2*s, o2 = y2*c + y1*s;
    if (!which) { o1 *= 0.125f; o2 *= 0.125f; }
    size_t b = (size_t)row * DH;
    __nv_bfloat16* dh = which ? k_h : q_h;
    __nv_bfloat16* dl = which ? k_l : q_l;
    split2(o1, &dh[b+lane], &dl[b+lane]);
    split2(o2, &dh[b+lane+32], &dl[b+lane+32]);
}

// ---- silu(g)*u -> hi/lo ----
__global__ void __launch_bounds__(256) silu_k() {
    size_t i = ((size_t)blockIdx.x * 256 + threadIdx.x) * 4;
    float4 g = *(float4*)(g_g + i);
    float4 u = *(float4*)(g_u + i);
    split2(g.x / (1.f + expf(-g.x)) * u.x, &gg_h[i],   &gg_l[i]);
    split2(g.y / (1.f + expf(-g.y)) * u.y, &gg_h[i+1], &gg_l[i+1]);
    split2(g.z / (1.f + expf(-g.z)) * u.z, &gg_h[i+2], &gg_l[i+2]);
    split2(g.w / (1.f + expf(-g.w)) * u.w, &gg_h[i+3], &gg_l[i+3]);
}

// ---- host ----
extern "C" void kernel_launch(void* const* d_in, const int* in_sizes, int n_in,
                              void* d_out, int out_size) {
    (void)in_sizes; (void)n_in; (void)out_size;
    const float* x      = (const float*)d_in[0];
    const int*   pos    = (const int*)d_in[1];
    const int*   tpos   = (const int*)d_in[2];
    const float* qkv_w  = (const float*)d_in[3];
    const float* qkv_b  = (const float*)d_in[4];
    const float* proj_w = (const float*)d_in[5];
    const float* proj_b = (const float*)d_in[6];
    const float* qn_w   = (const float*)d_in[7];
    const float* kn_w   = (const float*)d_in[8];
    const float* ln1_w  = (const float*)d_in[9];
    const float* ln2_w  = (const float*)d_in[10];
    const float* gate_w = (const float*)d_in[11];
    const float* up_w   = (const float*)d_in[12];
    const float* down_w = (const float*)d_in[13];
    float* out = (float*)d_out;

    const int S128 = 81920, S64 = 61440;
    cudaFuncSetAttribute(mmagemm_k<128,0>, cudaFuncAttributeMaxDynamicSharedMemorySize, S128);
    cudaFuncSetAttribute(mmagemm_k<64,3>,  cudaFuncAttributeMaxDynamicSharedMemorySize, S64);
    cudaFuncSetAttribute(mmagemm_k<128,7>, cudaFuncAttributeMaxDynamicSharedMemorySize, S128);
    cudaFuncSetAttribute(mmagemm_k<128,8>, cudaFuncAttributeMaxDynamicSharedMemorySize, S128);
    cudaFuncSetAttribute(flash_k, cudaFuncAttributeMaxDynamicSharedMemorySize, FSM);

    __nv_bfloat16 *wqh,*wql,*wph,*wpl,*wgh,*wgl,*wuh,*wul,*wdh,*wdl,*xh,*xl,*aoh,*aol,*ggh,*ggl;
    cudaGetSymbolAddress((void**)&wqh, wqkv_h); cudaGetSymbolAddress((void**)&wql, wqkv_l);
    cudaGetSymbolAddress((void**)&wph, wprj_h); cudaGetSymbolAddress((void**)&wpl, wprj_l);
    cudaGetSymbolAddress((void**)&wgh, wgat_h); cudaGetSymbolAddress((void**)&wgl, wgat_l);
    cudaGetSymbolAddress((void**)&wuh, wup_h);  cudaGetSymbolAddress((void**)&wul, wup_l);
    cudaGetSymbolAddress((void**)&wdh, wdn_h);  cudaGetSymbolAddress((void**)&wdl, wdn_l);
    cudaGetSymbolAddress((void**)&xh, xn_h);    cudaGetSymbolAddress((void**)&xl, xn_l);
    cudaGetSymbolAddress((void**)&aoh, ao_h);   cudaGetSymbolAddress((void**)&aol, ao_l);
    cudaGetSymbolAddress((void**)&ggh, gg_h);   cudaGetSymbolAddress((void**)&ggl, gg_l);
    float *fh;
    cudaGetSymbolAddress((void**)&fh, g_h);

    transconv_k<<<dim3(3072/128, 1024/32, 3), 256>>>(qkv_w,  wqh, wql, 1024, 3072);
    transconv_k<<<dim3(1024/128, 1024/32, 3), 256>>>(proj_w, wph, wpl, 1024, 1024);
    transconv_k<<<dim3(4096/128, 1024/32, 3), 256>>>(gate_w, wgh, wgl, 1024, 4096);
    transconv_k<<<dim3(4096/128, 1024/32, 3), 256>>>(up_w,   wuh, wul, 1024, 4096);
    transconv_k<<<dim3(1024/128, 4096/32, 3), 256>>>(down_w, wdh, wdl, 4096, 1024);

    rmsnorm_k<<<B_ * N_, 256>>>(x, xh, xl, ln1_w);
    mmagemm_k<128,0><<<dim3(24, 20, 1), 256, S128>>>(xh, xl, wqh, wql, qkv_b, nullptr, nullptr, 1024, 1024, 0, (long)3072*1024, 1);
    qkrope_k<<<(BH_ * N_ * 2) / 8, 256>>>(qn_w, kn_w, pos, tpos);
    // fused attention: scores + mask + softmax + PV -> ao
    flash_k<<<dim3(32, 10), 256, FSM>>>();
    mmagemm_k<64,3><<<dim3(16, 20, 1), 256, S64>>>(aoh, aol, wph, wpl, proj_b, x, nullptr, 1024, 1024, 0, (long)1024*1024, 1);
    rmsnorm_k<<<B_ * N_, 256>>>(fh, xh, xl, ln2_w);
    mmagemm_k<128,8><<<dim3(64, 20, 1), 256, S128>>>(xh, xl, wgh, wgl, (const float*)wuh, (const float*)wul, nullptr, 1024, 1024, 0, (long)4096*1024, 1);
    silu_k<<<(B_ * N_ * I_) / 1024, 256>>>();
    mmagemm_k<128,7><<<dim3(8, 20, 2), 256, S128>>>(ggh, ggl, wdh, wdl, nullptr, nullptr, nullptr, 2048, 4096, 0, (long)1024*4096, 1);
    reduce_k<<<(B_ * N_ * C_) / 1024, 256>>>(out);
}